// round 1
// baseline (speedup 1.0000x reference)
#include <cuda_runtime.h>
#include <math.h>

#define N_SAMPLES 131072
#define DIMS      16
#define DIMSC     16
#define UNITS     512
#define BINS      10
#define DT        8
#define FEAT_IN   24
#define FEAT_OUT  248
#define NBLOCKS   8
#define MIN_W     0.001f
#define MIN_H     0.001f
#define MIN_D     0.001f

#define MT        64      // samples per CTA
#define NTHREADS  512
#define KT        32      // K-chunk for weight staging

// smem layout (floats):
//  [0, 32768)       s_h   : 64 x 512 activation tile (h0, then overwritten by h1)
//  [32768, 49152)   s_w   : weight staging (16384 floats)
//  [49152, 50688)   s_in  : 64 x 24 subnet inputs
#define OFF_H   0
#define OFF_W   32768
#define OFF_IN  49152
#define SMEM_FLOATS 50688

__device__ float g_z[N_SAMPLES * DIMS];   // flow state scratch (8 MB)

__global__ void init_kernel(const float* __restrict__ x, float* __restrict__ out) {
    int i = blockIdx.x * blockDim.x + threadIdx.x;
    if (i < N_SAMPLES * DIMS) g_z[i] = x[i];
    if (i < N_SAMPLES) out[i] = 0.f;
}

// Insert bit `bit` at position p of 3-bit value f -> 4-bit dim index.
// Enumerates, in ascending order, the dims j with ((j>>p)&1)==bit.
__device__ __forceinline__ int insert_bit(int f, int p, int bit) {
    int lo = f & ((1 << p) - 1);
    int hi = f >> p;
    return (hi << (p + 1)) | (bit << p) | lo;
}

__global__ void __launch_bounds__(NTHREADS, 1)
flow_block_kernel(int b,
                  const float* __restrict__ c,
                  const float* __restrict__ W0, const float* __restrict__ b0,
                  const float* __restrict__ W1, const float* __restrict__ b1,
                  const float* __restrict__ W2, const float* __restrict__ b2,
                  float* __restrict__ out)
{
    extern __shared__ float smem[];
    float* s_h  = smem + OFF_H;
    float* s_w  = smem + OFF_W;
    float* s_in = smem + OFF_IN;

    const int tid  = threadIdx.x;
    const int row0 = blockIdx.x * MT;
    const int p    = b >> 1;
    const int cbit = 1 - (b & 1);   // conditional dims have bit_p == cbit

    // ---------------- Phase A: gather subnet inputs [64 x 24] ----------------
    for (int i = tid; i < MT * FEAT_IN; i += NTHREADS) {
        int m = i / FEAT_IN, f = i % FEAT_IN;
        float v;
        if (f < DT) v = g_z[(row0 + m) * DIMS + insert_bit(f, p, cbit)];
        else        v = c[(row0 + m) * DIMSC + (f - DT)];
        s_in[m * FEAT_IN + f] = v;
    }
    // stage W0 (24 x 512) fully into s_w
    {
        const float4* g4 = reinterpret_cast<const float4*>(W0);
        float4* s4 = reinterpret_cast<float4*>(s_w);
        #pragma unroll
        for (int i = 0; i < (FEAT_IN * UNITS / 4) / NTHREADS; i++)
            s4[tid + i * NTHREADS] = g4[tid + i * NTHREADS];
    }
    __syncthreads();

    const int mg = tid >> 6;   // 0..7  -> rows mg*8 .. mg*8+7
    const int ng = tid & 63;   // 0..63 -> cols ng + 64*j

    // ---------------- Phase B: layer0  h0 = relu(in @ W0 + b0) ----------------
    {
        float acc[8][8];
        float binit[8];
        #pragma unroll
        for (int j = 0; j < 8; j++) binit[j] = b0[ng + 64 * j];
        #pragma unroll
        for (int mi = 0; mi < 8; mi++)
            #pragma unroll
            for (int j = 0; j < 8; j++) acc[mi][j] = binit[j];
        #pragma unroll
        for (int k = 0; k < FEAT_IN; k++) {
            float a[8], bw[8];
            #pragma unroll
            for (int mi = 0; mi < 8; mi++) a[mi] = s_in[(mg * 8 + mi) * FEAT_IN + k];
            #pragma unroll
            for (int j = 0; j < 8; j++) bw[j] = s_w[k * UNITS + ng + 64 * j];
            #pragma unroll
            for (int mi = 0; mi < 8; mi++)
                #pragma unroll
                for (int j = 0; j < 8; j++) acc[mi][j] += a[mi] * bw[j];
        }
        #pragma unroll
        for (int mi = 0; mi < 8; mi++)
            #pragma unroll
            for (int j = 0; j < 8; j++)
                s_h[(mg * 8 + mi) * UNITS + ng + 64 * j] = fmaxf(acc[mi][j], 0.f);
    }

    // ---------------- Phase C: layer1  h1 = relu(h0 @ W1 + b1) ----------------
    {
        float acc[8][8];
        float binit[8];
        #pragma unroll
        for (int j = 0; j < 8; j++) binit[j] = b1[ng + 64 * j];
        #pragma unroll
        for (int mi = 0; mi < 8; mi++)
            #pragma unroll
            for (int j = 0; j < 8; j++) acc[mi][j] = binit[j];

        for (int kk = 0; kk < UNITS; kk += KT) {
            __syncthreads();   // prior phase done reading s_w / this chunk consumed
            const float4* g4 = reinterpret_cast<const float4*>(W1 + kk * UNITS);
            float4* s4 = reinterpret_cast<float4*>(s_w);
            #pragma unroll
            for (int i = 0; i < (KT * UNITS / 4) / NTHREADS; i++)
                s4[tid + i * NTHREADS] = g4[tid + i * NTHREADS];
            __syncthreads();
            #pragma unroll 4
            for (int k2 = 0; k2 < KT; k2++) {
                float a[8], bw[8];
                #pragma unroll
                for (int mi = 0; mi < 8; mi++)
                    a[mi] = s_h[(mg * 8 + mi) * UNITS + kk + k2];
                #pragma unroll
                for (int j = 0; j < 8; j++)
                    bw[j] = s_w[k2 * UNITS + ng + 64 * j];
                #pragma unroll
                for (int mi = 0; mi < 8; mi++)
                    #pragma unroll
                    for (int j = 0; j < 8; j++) acc[mi][j] += a[mi] * bw[j];
            }
        }
        __syncthreads();   // all reads of h0 complete before overwrite
        #pragma unroll
        for (int mi = 0; mi < 8; mi++)
            #pragma unroll
            for (int j = 0; j < 8; j++)
                s_h[(mg * 8 + mi) * UNITS + ng + 64 * j] = fmaxf(acc[mi][j], 0.f);
    }

    // ---------------- Phase D: layer2  params = h1 @ W2 + b2 ----------------
    // thread owns one (sample m2, spline dim dg) pair -> 31 params in registers
    const int m2 = tid >> 3;   // 0..63
    const int dg = tid & 7;    // 0..7
    float pr[31];
    #pragma unroll
    for (int j = 0; j < 31; j++) pr[j] = b2[dg * 31 + j];

    for (int kk = 0; kk < UNITS; kk += KT) {
        __syncthreads();
        // stage W2 chunk with per-dim padded layout: s_w[k2*256 + dg*32 + j]
        for (int i = tid; i < KT * FEAT_OUT; i += NTHREADS) {
            int k2 = i / FEAT_OUT, n = i % FEAT_OUT;
            int dd_ = n / 31, jj = n % 31;
            s_w[k2 * 256 + dd_ * 32 + jj] = W2[(kk + k2) * FEAT_OUT + n];
        }
        __syncthreads();
        #pragma unroll 4
        for (int k2 = 0; k2 < KT; k2++) {
            float a = s_h[m2 * UNITS + kk + k2];
            const float* wrow = s_w + k2 * 256 + dg * 32;
            const float4* w4 = reinterpret_cast<const float4*>(wrow);
            #pragma unroll
            for (int q = 0; q < 7; q++) {
                float4 v = w4[q];
                pr[4 * q + 0] += a * v.x;
                pr[4 * q + 1] += a * v.y;
                pr[4 * q + 2] += a * v.z;
                pr[4 * q + 3] += a * v.w;
            }
            pr[28] += a * wrow[28];
            pr[29] += a * wrow[29];
            pr[30] += a * wrow[30];
        }
    }

    // ---------------- Phase E: RQS spline + logdet ----------------
    {
        const int tdim = insert_bit(dg, p, 1 - cbit);
        const float xv = g_z[(row0 + m2) * DIMS + tdim];

        float w[BINS], hh[BINS], dd[BINS + 1];

        // widths: MIN_W + (1 - MIN_W*BINS) * softmax(pr[0:10])
        float mx = pr[0];
        #pragma unroll
        for (int i = 1; i < BINS; i++) mx = fmaxf(mx, pr[i]);
        float ssum = 0.f;
        #pragma unroll
        for (int i = 0; i < BINS; i++) { w[i] = expf(pr[i] - mx); ssum += w[i]; }
        float sc = (1.0f - MIN_W * (float)BINS) / ssum;
        #pragma unroll
        for (int i = 0; i < BINS; i++) w[i] = MIN_W + w[i] * sc;

        // heights
        mx = pr[BINS];
        #pragma unroll
        for (int i = 1; i < BINS; i++) mx = fmaxf(mx, pr[BINS + i]);
        ssum = 0.f;
        #pragma unroll
        for (int i = 0; i < BINS; i++) { hh[i] = expf(pr[BINS + i] - mx); ssum += hh[i]; }
        sc = (1.0f - MIN_H * (float)BINS) / ssum;
        #pragma unroll
        for (int i = 0; i < BINS; i++) hh[i] = MIN_H + hh[i] * sc;

        // derivatives: MIN_D + softplus(pr[20:31])  (stable softplus)
        #pragma unroll
        for (int i = 0; i <= BINS; i++) {
            float u = pr[2 * BINS + i];
            dd[i] = MIN_D + (fmaxf(u, 0.f) + log1pf(expf(-fabsf(u))));
        }

        // cumulative knots
        float cw[BINS + 1], ch[BINS + 1];
        cw[0] = 0.f; ch[0] = 0.f;
        #pragma unroll
        for (int i = 1; i <= BINS; i++) { cw[i] = cw[i - 1] + w[i - 1]; ch[i] = ch[i - 1] + hh[i - 1]; }

        int cnt = 0;
        #pragma unroll
        for (int i = 0; i <= BINS; i++) cnt += (xv >= cw[i]) ? 1 : 0;
        int idx = cnt - 1;
        idx = idx < 0 ? 0 : (idx > BINS - 1 ? BINS - 1 : idx);

        float xk = 0.f, wk = 1.f, yk = 0.f, hk = 1.f, dk = 1.f, dk1 = 1.f;
        #pragma unroll
        for (int i = 0; i < BINS; i++) {
            if (i == idx) { xk = cw[i]; wk = w[i]; yk = ch[i]; hk = hh[i]; dk = dd[i]; dk1 = dd[i + 1]; }
        }

        float th  = fminf(fmaxf((xv - xk) / wk, 0.f), 1.f);
        float sr  = hk / wk;
        float t1  = th * (1.f - th);
        float den = sr + (dk1 + dk - 2.f * sr) * t1;
        float y   = yk + hk * (sr * th * th + dk * t1) / den;
        float omt = 1.f - th;
        float ld  = 2.f * logf(sr)
                  + logf(dk1 * th * th + 2.f * sr * t1 + dk * omt * omt)
                  - 2.f * logf(den);

        g_z[(row0 + m2) * DIMS + tdim] = y;

        // reduce logdet over the 8 spline dims (consecutive lanes)
        #pragma unroll
        for (int off = 4; off > 0; off >>= 1)
            ld += __shfl_down_sync(0xffffffffu, ld, off);
        if (dg == 0) out[row0 + m2] += ld;
    }
}

extern "C" void kernel_launch(void* const* d_in, const int* in_sizes, int n_in,
                              void* d_out, int out_size) {
    const float* x  = (const float*)d_in[0];
    const float* c  = (const float*)d_in[1];
    const float* W0 = (const float*)d_in[2];
    const float* b0 = (const float*)d_in[3];
    const float* W1 = (const float*)d_in[4];
    const float* b1 = (const float*)d_in[5];
    const float* W2 = (const float*)d_in[6];
    const float* b2 = (const float*)d_in[7];
    float* out = (float*)d_out;

    size_t smem = (size_t)SMEM_FLOATS * sizeof(float);
    cudaFuncSetAttribute(flow_block_kernel,
                         cudaFuncAttributeMaxDynamicSharedMemorySize, (int)smem);

    init_kernel<<<(N_SAMPLES * DIMS + 255) / 256, 256>>>(x, out);

    for (int b = 0; b < NBLOCKS; b++) {
        flow_block_kernel<<<N_SAMPLES / MT, NTHREADS, smem>>>(
            b, c,
            W0 + (size_t)b * FEAT_IN * UNITS,
            b0 + (size_t)b * UNITS,
            W1 + (size_t)b * UNITS * UNITS,
            b1 + (size_t)b * UNITS,
            W2 + (size_t)b * UNITS * FEAT_OUT,
            b2 + (size_t)b * FEAT_OUT,
            out);
    }
}

// round 2
// speedup vs baseline: 8.1826x; 8.1826x over previous
#include <cuda_runtime.h>
#include <math.h>
#include <stdint.h>

#define N_SAMPLES 131072
#define DIMS      16
#define DIMSC     16
#define UNITS     512
#define BINS      10
#define DT        8
#define FEAT_IN   24
#define FEAT_OUT  248
#define NBLOCKS   8
#define MIN_W     0.001f
#define MIN_H     0.001f
#define MIN_D     0.001f

#define MT        64
#define NTHREADS  512
#define KT        16

// smem layout (floats):
//  [0, 32768)       s_ht : transposed activation tile [512][64] (h0 then h1, then params)
//  [32768, 49152)   s_w  : weight staging (two buffers)
//  [49152, 50688)   s_in : transposed subnet inputs [24][64]
#define OFF_HT 0
#define OFF_W  32768
#define OFF_IN 49152
#define SMEM_FLOATS 50688

__device__ float g_z[N_SAMPLES * DIMS];

__global__ void init_kernel(const float* __restrict__ x, float* __restrict__ out) {
    int i = blockIdx.x * blockDim.x + threadIdx.x;
    if (i < N_SAMPLES * DIMS) g_z[i] = x[i];
    if (i < N_SAMPLES) out[i] = 0.f;
}

__device__ __forceinline__ int insert_bit(int f, int p, int bit) {
    int lo = f & ((1 << p) - 1);
    int hi = f >> p;
    return (hi << (p + 1)) | (bit << p) | lo;
}

__device__ __forceinline__ uint32_t smem_u32(const void* p) {
    return (uint32_t)__cvta_generic_to_shared(p);
}
#define CP16(s, g)  asm volatile("cp.async.cg.shared.global [%0], [%1], 16;" :: "r"(s), "l"(g))
#define CPCOMMIT()  asm volatile("cp.async.commit_group;")
#define CPWAIT1()   asm volatile("cp.async.wait_group 1;" ::: "memory")
#define CPWAIT0()   asm volatile("cp.async.wait_group 0;" ::: "memory")

__global__ void __launch_bounds__(NTHREADS, 1)
flow_block_kernel(int blk,
                  const float* __restrict__ cc,
                  const float* __restrict__ W0, const float* __restrict__ B0,
                  const float* __restrict__ W1, const float* __restrict__ B1,
                  const float* __restrict__ W2, const float* __restrict__ B2,
                  float* __restrict__ out)
{
    extern __shared__ float smem[];
    float* s_ht = smem + OFF_HT;
    float* s_w  = smem + OFF_W;
    float* s_in = smem + OFF_IN;

    const int tid  = threadIdx.x;
    const int w    = tid >> 5;
    const int lane = tid & 31;
    const int tm4  = (lane & 7) * 4;          // m quadrant base: tm4 and tm4+32
    const int nb   = w * 16 + (lane >> 3) * 4; // n base (0..252)
    const int row0 = blockIdx.x * MT;
    const int p    = blk >> 1;
    const int cbit = 1 - (blk & 1);

    // ---------------- Phase A: stage W0 (async) + gather inputs (transposed) ----
    {
        uint32_t sdst = smem_u32(s_w) + tid * 16;
        const float4* g4 = (const float4*)W0;
        #pragma unroll
        for (int i = 0; i < (FEAT_IN * UNITS / 4) / NTHREADS; i++)   // 6
            CP16(sdst + i * NTHREADS * 16, (const void*)(g4 + tid + i * NTHREADS));
        CPCOMMIT();
    }
    for (int i = tid; i < MT * FEAT_IN; i += NTHREADS) {
        int f = i >> 6, m = i & 63;
        float v = (f < DT) ? g_z[(row0 + m) * DIMS + insert_bit(f, p, cbit)]
                           : cc[(row0 + m) * DIMSC + (f - DT)];
        s_in[f * 64 + m] = v;
    }
    CPWAIT0();
    __syncthreads();

    float acc[8][8];

    // ---------------- Phase B: h0 = relu(in @ W0 + b0), K=24 ----------------
    {
        float4 q0 = *(const float4*)(B0 + nb);
        float4 q1 = *(const float4*)(B0 + nb + 256);
        float bv[8] = {q0.x,q0.y,q0.z,q0.w,q1.x,q1.y,q1.z,q1.w};
        #pragma unroll
        for (int mi = 0; mi < 8; mi++)
            #pragma unroll
            for (int nj = 0; nj < 8; nj++) acc[mi][nj] = bv[nj];
    }
    #pragma unroll
    for (int k = 0; k < FEAT_IN; k++) {
        float4 a0 = *(const float4*)(s_in + k * 64 + tm4);
        float4 a1 = *(const float4*)(s_in + k * 64 + tm4 + 32);
        float4 f0 = *(const float4*)(s_w + k * UNITS + nb);
        float4 f1 = *(const float4*)(s_w + k * UNITS + nb + 256);
        float av[8] = {a0.x,a0.y,a0.z,a0.w,a1.x,a1.y,a1.z,a1.w};
        float wv[8] = {f0.x,f0.y,f0.z,f0.w,f1.x,f1.y,f1.z,f1.w};
        #pragma unroll
        for (int mi = 0; mi < 8; mi++)
            #pragma unroll
            for (int nj = 0; nj < 8; nj++)
                acc[mi][nj] = fmaf(av[mi], wv[nj], acc[mi][nj]);
    }
    __syncthreads();   // all reads of s_w (W0) done before chunk0 overwrite

    // store h0 transposed with relu: s_ht[n*64 + m]
    #pragma unroll
    for (int nj = 0; nj < 8; nj++) {
        int n = nb + (nj & 3) + ((nj >> 2) << 8);
        float4 v0 = make_float4(fmaxf(acc[0][nj],0.f), fmaxf(acc[1][nj],0.f),
                                fmaxf(acc[2][nj],0.f), fmaxf(acc[3][nj],0.f));
        float4 v1 = make_float4(fmaxf(acc[4][nj],0.f), fmaxf(acc[5][nj],0.f),
                                fmaxf(acc[6][nj],0.f), fmaxf(acc[7][nj],0.f));
        *(float4*)(s_ht + n * 64 + tm4)      = v0;
        *(float4*)(s_ht + n * 64 + tm4 + 32) = v1;
    }
    __syncthreads();

    // ---------------- Phase C: h1 = relu(h0 @ W1 + b1), K=512 ----------------
    {
        float4 q0 = *(const float4*)(B1 + nb);
        float4 q1 = *(const float4*)(B1 + nb + 256);
        float bv[8] = {q0.x,q0.y,q0.z,q0.w,q1.x,q1.y,q1.z,q1.w};
        #pragma unroll
        for (int mi = 0; mi < 8; mi++)
            #pragma unroll
            for (int nj = 0; nj < 8; nj++) acc[mi][nj] = bv[nj];
    }
    // prefetch W1 chunk 0 into buffer 0
    {
        uint32_t sdst = smem_u32(s_w) + tid * 16;
        const float4* g4 = (const float4*)W1;
        #pragma unroll
        for (int i = 0; i < (KT * UNITS / 4) / NTHREADS; i++)   // 4
            CP16(sdst + i * NTHREADS * 16, (const void*)(g4 + tid + i * NTHREADS));
        CPCOMMIT();
    }
    for (int ck = 0; ck < UNITS / KT; ck++) {
        const float* buf = s_w + (ck & 1) * (KT * UNITS);
        if (ck < UNITS / KT - 1) {
            uint32_t sdst = smem_u32(s_w + ((ck + 1) & 1) * (KT * UNITS)) + tid * 16;
            const float4* g4 = (const float4*)(W1 + (ck + 1) * KT * UNITS);
            #pragma unroll
            for (int i = 0; i < (KT * UNITS / 4) / NTHREADS; i++)
                CP16(sdst + i * NTHREADS * 16, (const void*)(g4 + tid + i * NTHREADS));
        } else {
            // last iter: prefetch W2 chunk 0 into buffer 0 (chunk 30 compute done)
            for (int i = tid; i < (KT * FEAT_OUT) / 4; i += NTHREADS)
                CP16(smem_u32(s_w) + i * 16, (const void*)((const float4*)W2 + i));
        }
        CPCOMMIT();
        CPWAIT1();
        __syncthreads();
        const int kb = ck * KT;
        #pragma unroll
        for (int k2 = 0; k2 < KT; k2++) {
            float4 a0 = *(const float4*)(s_ht + (kb + k2) * 64 + tm4);
            float4 a1 = *(const float4*)(s_ht + (kb + k2) * 64 + tm4 + 32);
            float4 f0 = *(const float4*)(buf + k2 * UNITS + nb);
            float4 f1 = *(const float4*)(buf + k2 * UNITS + nb + 256);
            float av[8] = {a0.x,a0.y,a0.z,a0.w,a1.x,a1.y,a1.z,a1.w};
            float wv[8] = {f0.x,f0.y,f0.z,f0.w,f1.x,f1.y,f1.z,f1.w};
            #pragma unroll
            for (int mi = 0; mi < 8; mi++)
                #pragma unroll
                for (int nj = 0; nj < 8; nj++)
                    acc[mi][nj] = fmaf(av[mi], wv[nj], acc[mi][nj]);
        }
        __syncthreads();
    }
    // store h1 transposed with relu (h0 fully consumed)
    #pragma unroll
    for (int nj = 0; nj < 8; nj++) {
        int n = nb + (nj & 3) + ((nj >> 2) << 8);
        float4 v0 = make_float4(fmaxf(acc[0][nj],0.f), fmaxf(acc[1][nj],0.f),
                                fmaxf(acc[2][nj],0.f), fmaxf(acc[3][nj],0.f));
        float4 v1 = make_float4(fmaxf(acc[4][nj],0.f), fmaxf(acc[5][nj],0.f),
                                fmaxf(acc[6][nj],0.f), fmaxf(acc[7][nj],0.f));
        *(float4*)(s_ht + n * 64 + tm4)      = v0;
        *(float4*)(s_ht + n * 64 + tm4 + 32) = v1;
    }
    __syncthreads();

    // ---------------- Phase D: params = h1 @ W2 + b2  (64 x 256-padded GEMM) ----
    // thread computes 8 m x 4 n; n = nb..nb+3 (0..255 across warps; n>=248 unused)
    float acc2[8][4];
    #pragma unroll
    for (int mi = 0; mi < 8; mi++)
        #pragma unroll
        for (int nj = 0; nj < 4; nj++) acc2[mi][nj] = 0.f;

    for (int ck = 0; ck < UNITS / KT; ck++) {
        const float* buf = s_w + (ck & 1) * 4096;
        if (ck < UNITS / KT - 1) {
            uint32_t sbase = smem_u32(s_w + ((ck + 1) & 1) * 4096);
            const float4* g4 = (const float4*)(W2 + (ck + 1) * KT * FEAT_OUT);
            for (int i = tid; i < (KT * FEAT_OUT) / 4; i += NTHREADS)
                CP16(sbase + i * 16, (const void*)(g4 + i));
        }
        CPCOMMIT();
        CPWAIT1();
        __syncthreads();
        const int kb = ck * KT;
        #pragma unroll
        for (int k2 = 0; k2 < KT; k2++) {
            float4 a0 = *(const float4*)(s_ht + (kb + k2) * 64 + tm4);
            float4 a1 = *(const float4*)(s_ht + (kb + k2) * 64 + tm4 + 32);
            float4 f0 = *(const float4*)(buf + k2 * FEAT_OUT + nb);
            float av[8] = {a0.x,a0.y,a0.z,a0.w,a1.x,a1.y,a1.z,a1.w};
            float wv[4] = {f0.x,f0.y,f0.z,f0.w};
            #pragma unroll
            for (int mi = 0; mi < 8; mi++)
                #pragma unroll
                for (int nj = 0; nj < 4; nj++)
                    acc2[mi][nj] = fmaf(av[mi], wv[nj], acc2[mi][nj]);
        }
        __syncthreads();
    }

    // park params in smem (h1 dead): s_p[m*256 + n]
    #pragma unroll
    for (int mi = 0; mi < 8; mi++) {
        int m = tm4 + (mi & 3) + ((mi >> 2) << 5);
        *(float4*)(s_ht + m * 256 + nb) =
            make_float4(acc2[mi][0], acc2[mi][1], acc2[mi][2], acc2[mi][3]);
    }
    __syncthreads();

    // ---------------- Phase E: RQS spline + logdet ----------------
    {
        const int m2 = tid >> 3;
        const int dg = tid & 7;
        float pr[31];
        #pragma unroll
        for (int j = 0; j < 31; j++)
            pr[j] = s_ht[m2 * 256 + dg * 31 + j] + B2[dg * 31 + j];

        const int tdim = insert_bit(dg, p, 1 - cbit);
        const float xv = g_z[(row0 + m2) * DIMS + tdim];

        float ww[BINS], hh[BINS], dd[BINS + 1];

        float mx = pr[0];
        #pragma unroll
        for (int i = 1; i < BINS; i++) mx = fmaxf(mx, pr[i]);
        float ssum = 0.f;
        #pragma unroll
        for (int i = 0; i < BINS; i++) { ww[i] = expf(pr[i] - mx); ssum += ww[i]; }
        float sc = (1.0f - MIN_W * (float)BINS) / ssum;
        #pragma unroll
        for (int i = 0; i < BINS; i++) ww[i] = MIN_W + ww[i] * sc;

        mx = pr[BINS];
        #pragma unroll
        for (int i = 1; i < BINS; i++) mx = fmaxf(mx, pr[BINS + i]);
        ssum = 0.f;
        #pragma unroll
        for (int i = 0; i < BINS; i++) { hh[i] = expf(pr[BINS + i] - mx); ssum += hh[i]; }
        sc = (1.0f - MIN_H * (float)BINS) / ssum;
        #pragma unroll
        for (int i = 0; i < BINS; i++) hh[i] = MIN_H + hh[i] * sc;

        #pragma unroll
        for (int i = 0; i <= BINS; i++) {
            float u = pr[2 * BINS + i];
            dd[i] = MIN_D + (fmaxf(u, 0.f) + log1pf(expf(-fabsf(u))));
        }

        float cw[BINS + 1], ch[BINS + 1];
        cw[0] = 0.f; ch[0] = 0.f;
        #pragma unroll
        for (int i = 1; i <= BINS; i++) { cw[i] = cw[i-1] + ww[i-1]; ch[i] = ch[i-1] + hh[i-1]; }

        int cnt = 0;
        #pragma unroll
        for (int i = 0; i <= BINS; i++) cnt += (xv >= cw[i]) ? 1 : 0;
        int idx = cnt - 1;
        idx = idx < 0 ? 0 : (idx > BINS - 1 ? BINS - 1 : idx);

        float xk = 0.f, wk = 1.f, yk = 0.f, hk = 1.f, dk = 1.f, dk1 = 1.f;
        #pragma unroll
        for (int i = 0; i < BINS; i++) {
            if (i == idx) { xk = cw[i]; wk = ww[i]; yk = ch[i]; hk = hh[i]; dk = dd[i]; dk1 = dd[i+1]; }
        }

        float th  = fminf(fmaxf((xv - xk) / wk, 0.f), 1.f);
        float sr  = hk / wk;
        float t1  = th * (1.f - th);
        float den = sr + (dk1 + dk - 2.f * sr) * t1;
        float y   = yk + hk * (sr * th * th + dk * t1) / den;
        float omt = 1.f - th;
        float ld  = 2.f * logf(sr)
                  + logf(dk1 * th * th + 2.f * sr * t1 + dk * omt * omt)
                  - 2.f * logf(den);

        g_z[(row0 + m2) * DIMS + tdim] = y;

        #pragma unroll
        for (int off = 4; off > 0; off >>= 1)
            ld += __shfl_down_sync(0xffffffffu, ld, off);
        if (dg == 0) out[row0 + m2] += ld;
    }
}

extern "C" void kernel_launch(void* const* d_in, const int* in_sizes, int n_in,
                              void* d_out, int out_size) {
    const float* x  = (const float*)d_in[0];
    const float* c  = (const float*)d_in[1];
    const float* W0 = (const float*)d_in[2];
    const float* b0 = (const float*)d_in[3];
    const float* W1 = (const float*)d_in[4];
    const float* b1 = (const float*)d_in[5];
    const float* W2 = (const float*)d_in[6];
    const float* b2 = (const float*)d_in[7];
    float* out = (float*)d_out;

    size_t smem = (size_t)SMEM_FLOATS * sizeof(float);
    cudaFuncSetAttribute(flow_block_kernel,
                         cudaFuncAttributeMaxDynamicSharedMemorySize, (int)smem);

    init_kernel<<<(N_SAMPLES * DIMS + 255) / 256, 256>>>(x, out);

    for (int b = 0; b < NBLOCKS; b++) {
        flow_block_kernel<<<N_SAMPLES / MT, NTHREADS, smem>>>(
            b, c,
            W0 + (size_t)b * FEAT_IN * UNITS,
            b0 + (size_t)b * UNITS,
            W1 + (size_t)b * UNITS * UNITS,
            b1 + (size_t)b * UNITS,
            W2 + (size_t)b * UNITS * FEAT_OUT,
            b2 + (size_t)b * FEAT_OUT,
            out);
    }
}

// round 3
// speedup vs baseline: 8.1884x; 1.0007x over previous
#include <cuda_runtime.h>
#include <math.h>
#include <stdint.h>

#define N_SAMPLES 131072
#define DIMS      16
#define DIMSC     16
#define UNITS     512
#define BINS      10
#define DT        8
#define FEAT_IN   24
#define FEAT_OUT  248
#define NBLOCKS   8
#define MIN_W     0.001f
#define MIN_H     0.001f
#define MIN_D     0.001f

#define MT        64
#define NTHREADS  512
#define KT        16

// smem layout (floats):
//  [0, 32768)       s_ht : transposed activation tile [512][64] (h0 then h1, then params)
//  [32768, 49152)   s_w  : weight staging (two buffers)
//  [49152, 50688)   s_in : transposed subnet inputs [24][64]
#define OFF_HT 0
#define OFF_W  32768
#define OFF_IN 49152
#define SMEM_FLOATS 50688

__device__ float g_z[N_SAMPLES * DIMS];

__global__ void init_kernel(const float* __restrict__ x, float* __restrict__ out) {
    int i = blockIdx.x * blockDim.x + threadIdx.x;
    if (i < N_SAMPLES * DIMS) g_z[i] = x[i];
    if (i < N_SAMPLES) out[i] = 0.f;
}

__device__ __forceinline__ int insert_bit(int f, int p, int bit) {
    int lo = f & ((1 << p) - 1);
    int hi = f >> p;
    return (hi << (p + 1)) | (bit << p) | lo;
}

__device__ __forceinline__ uint32_t smem_u32(const void* p) {
    return (uint32_t)__cvta_generic_to_shared(p);
}
#define CP16(s, g)  asm volatile("cp.async.cg.shared.global [%0], [%1], 16;" :: "r"(s), "l"(g))
#define CPCOMMIT()  asm volatile("cp.async.commit_group;")
#define CPWAIT1()   asm volatile("cp.async.wait_group 1;" ::: "memory")
#define CPWAIT0()   asm volatile("cp.async.wait_group 0;" ::: "memory")

__global__ void __launch_bounds__(NTHREADS, 1)
flow_block_kernel(int blk,
                  const float* __restrict__ cc,
                  const float* __restrict__ W0, const float* __restrict__ B0,
                  const float* __restrict__ W1, const float* __restrict__ B1,
                  const float* __restrict__ W2, const float* __restrict__ B2,
                  float* __restrict__ out)
{
    extern __shared__ float smem[];
    float* s_ht = smem + OFF_HT;
    float* s_w  = smem + OFF_W;
    float* s_in = smem + OFF_IN;

    const int tid  = threadIdx.x;
    const int w    = tid >> 5;
    const int lane = tid & 31;
    const int tm4  = (lane & 7) * 4;          // m quadrant base: tm4 and tm4+32
    const int nb   = w * 16 + (lane >> 3) * 4; // n base (0..252)
    const int row0 = blockIdx.x * MT;
    const int p    = blk >> 1;
    const int cbit = 1 - (blk & 1);

    // ---------------- Phase A: stage W0 (async) + gather inputs (transposed) ----
    {
        uint32_t sdst = smem_u32(s_w) + tid * 16;
        const float4* g4 = (const float4*)W0;
        #pragma unroll
        for (int i = 0; i < (FEAT_IN * UNITS / 4) / NTHREADS; i++)   // 6
            CP16(sdst + i * NTHREADS * 16, (const void*)(g4 + tid + i * NTHREADS));
        CPCOMMIT();
    }
    for (int i = tid; i < MT * FEAT_IN; i += NTHREADS) {
        int f = i >> 6, m = i & 63;
        float v = (f < DT) ? g_z[(row0 + m) * DIMS + insert_bit(f, p, cbit)]
                           : cc[(row0 + m) * DIMSC + (f - DT)];
        s_in[f * 64 + m] = v;
    }
    CPWAIT0();
    __syncthreads();

    float acc[8][8];

    // ---------------- Phase B: h0 = relu(in @ W0 + b0), K=24 ----------------
    {
        float4 q0 = *(const float4*)(B0 + nb);
        float4 q1 = *(const float4*)(B0 + nb + 256);
        float bv[8] = {q0.x,q0.y,q0.z,q0.w,q1.x,q1.y,q1.z,q1.w};
        #pragma unroll
        for (int mi = 0; mi < 8; mi++)
            #pragma unroll
            for (int nj = 0; nj < 8; nj++) acc[mi][nj] = bv[nj];
    }
    #pragma unroll
    for (int k = 0; k < FEAT_IN; k++) {
        float4 a0 = *(const float4*)(s_in + k * 64 + tm4);
        float4 a1 = *(const float4*)(s_in + k * 64 + tm4 + 32);
        float4 f0 = *(const float4*)(s_w + k * UNITS + nb);
        float4 f1 = *(const float4*)(s_w + k * UNITS + nb + 256);
        float av[8] = {a0.x,a0.y,a0.z,a0.w,a1.x,a1.y,a1.z,a1.w};
        float wv[8] = {f0.x,f0.y,f0.z,f0.w,f1.x,f1.y,f1.z,f1.w};
        #pragma unroll
        for (int mi = 0; mi < 8; mi++)
            #pragma unroll
            for (int nj = 0; nj < 8; nj++)
                acc[mi][nj] = fmaf(av[mi], wv[nj], acc[mi][nj]);
    }
    __syncthreads();   // all reads of s_w (W0) done before chunk0 overwrite

    // store h0 transposed with relu: s_ht[n*64 + m]
    #pragma unroll
    for (int nj = 0; nj < 8; nj++) {
        int n = nb + (nj & 3) + ((nj >> 2) << 8);
        float4 v0 = make_float4(fmaxf(acc[0][nj],0.f), fmaxf(acc[1][nj],0.f),
                                fmaxf(acc[2][nj],0.f), fmaxf(acc[3][nj],0.f));
        float4 v1 = make_float4(fmaxf(acc[4][nj],0.f), fmaxf(acc[5][nj],0.f),
                                fmaxf(acc[6][nj],0.f), fmaxf(acc[7][nj],0.f));
        *(float4*)(s_ht + n * 64 + tm4)      = v0;
        *(float4*)(s_ht + n * 64 + tm4 + 32) = v1;
    }
    __syncthreads();

    // ---------------- Phase C: h1 = relu(h0 @ W1 + b1), K=512 ----------------
    {
        float4 q0 = *(const float4*)(B1 + nb);
        float4 q1 = *(const float4*)(B1 + nb + 256);
        float bv[8] = {q0.x,q0.y,q0.z,q0.w,q1.x,q1.y,q1.z,q1.w};
        #pragma unroll
        for (int mi = 0; mi < 8; mi++)
            #pragma unroll
            for (int nj = 0; nj < 8; nj++) acc[mi][nj] = bv[nj];
    }
    // prefetch W1 chunk 0 into buffer 0
    {
        uint32_t sdst = smem_u32(s_w) + tid * 16;
        const float4* g4 = (const float4*)W1;
        #pragma unroll
        for (int i = 0; i < (KT * UNITS / 4) / NTHREADS; i++)   // 4
            CP16(sdst + i * NTHREADS * 16, (const void*)(g4 + tid + i * NTHREADS));
        CPCOMMIT();
    }
    for (int ck = 0; ck < UNITS / KT; ck++) {
        const float* buf = s_w + (ck & 1) * (KT * UNITS);
        if (ck < UNITS / KT - 1) {
            uint32_t sdst = smem_u32(s_w + ((ck + 1) & 1) * (KT * UNITS)) + tid * 16;
            const float4* g4 = (const float4*)(W1 + (ck + 1) * KT * UNITS);
            #pragma unroll
            for (int i = 0; i < (KT * UNITS / 4) / NTHREADS; i++)
                CP16(sdst + i * NTHREADS * 16, (const void*)(g4 + tid + i * NTHREADS));
        } else {
            // last iter: prefetch W2 chunk 0 into buffer 0 (chunk 30 compute done)
            for (int i = tid; i < (KT * FEAT_OUT) / 4; i += NTHREADS)
                CP16(smem_u32(s_w) + i * 16, (const void*)((const float4*)W2 + i));
        }
        CPCOMMIT();
        CPWAIT1();
        __syncthreads();
        const int kb = ck * KT;
        #pragma unroll
        for (int k2 = 0; k2 < KT; k2++) {
            float4 a0 = *(const float4*)(s_ht + (kb + k2) * 64 + tm4);
            float4 a1 = *(const float4*)(s_ht + (kb + k2) * 64 + tm4 + 32);
            float4 f0 = *(const float4*)(buf + k2 * UNITS + nb);
            float4 f1 = *(const float4*)(buf + k2 * UNITS + nb + 256);
            float av[8] = {a0.x,a0.y,a0.z,a0.w,a1.x,a1.y,a1.z,a1.w};
            float wv[8] = {f0.x,f0.y,f0.z,f0.w,f1.x,f1.y,f1.z,f1.w};
            #pragma unroll
            for (int mi = 0; mi < 8; mi++)
                #pragma unroll
                for (int nj = 0; nj < 8; nj++)
                    acc[mi][nj] = fmaf(av[mi], wv[nj], acc[mi][nj]);
        }
        __syncthreads();
    }
    // store h1 transposed with relu (h0 fully consumed)
    #pragma unroll
    for (int nj = 0; nj < 8; nj++) {
        int n = nb + (nj & 3) + ((nj >> 2) << 8);
        float4 v0 = make_float4(fmaxf(acc[0][nj],0.f), fmaxf(acc[1][nj],0.f),
                                fmaxf(acc[2][nj],0.f), fmaxf(acc[3][nj],0.f));
        float4 v1 = make_float4(fmaxf(acc[4][nj],0.f), fmaxf(acc[5][nj],0.f),
                                fmaxf(acc[6][nj],0.f), fmaxf(acc[7][nj],0.f));
        *(float4*)(s_ht + n * 64 + tm4)      = v0;
        *(float4*)(s_ht + n * 64 + tm4 + 32) = v1;
    }
    __syncthreads();

    // ---------------- Phase D: params = h1 @ W2 + b2  (64 x 256-padded GEMM) ----
    // thread computes 8 m x 4 n; n = nb..nb+3 (0..255 across warps; n>=248 unused)
    float acc2[8][4];
    #pragma unroll
    for (int mi = 0; mi < 8; mi++)
        #pragma unroll
        for (int nj = 0; nj < 4; nj++) acc2[mi][nj] = 0.f;

    for (int ck = 0; ck < UNITS / KT; ck++) {
        const float* buf = s_w + (ck & 1) * 4096;
        if (ck < UNITS / KT - 1) {
            uint32_t sbase = smem_u32(s_w + ((ck + 1) & 1) * 4096);
            const float4* g4 = (const float4*)(W2 + (ck + 1) * KT * FEAT_OUT);
            for (int i = tid; i < (KT * FEAT_OUT) / 4; i += NTHREADS)
                CP16(sbase + i * 16, (const void*)(g4 + i));
        }
        CPCOMMIT();
        CPWAIT1();
        __syncthreads();
        const int kb = ck * KT;
        #pragma unroll
        for (int k2 = 0; k2 < KT; k2++) {
            float4 a0 = *(const float4*)(s_ht + (kb + k2) * 64 + tm4);
            float4 a1 = *(const float4*)(s_ht + (kb + k2) * 64 + tm4 + 32);
            float4 f0 = *(const float4*)(buf + k2 * FEAT_OUT + nb);
            float av[8] = {a0.x,a0.y,a0.z,a0.w,a1.x,a1.y,a1.z,a1.w};
            float wv[4] = {f0.x,f0.y,f0.z,f0.w};
            #pragma unroll
            for (int mi = 0; mi < 8; mi++)
                #pragma unroll
                for (int nj = 0; nj < 4; nj++)
                    acc2[mi][nj] = fmaf(av[mi], wv[nj], acc2[mi][nj]);
        }
        __syncthreads();
    }

    // park params in smem (h1 dead): s_p[m*256 + n]
    #pragma unroll
    for (int mi = 0; mi < 8; mi++) {
        int m = tm4 + (mi & 3) + ((mi >> 2) << 5);
        *(float4*)(s_ht + m * 256 + nb) =
            make_float4(acc2[mi][0], acc2[mi][1], acc2[mi][2], acc2[mi][3]);
    }
    __syncthreads();

    // ---------------- Phase E: RQS spline + logdet ----------------
    {
        const int m2 = tid >> 3;
        const int dg = tid & 7;
        float pr[31];
        #pragma unroll
        for (int j = 0; j < 31; j++)
            pr[j] = s_ht[m2 * 256 + dg * 31 + j] + B2[dg * 31 + j];

        const int tdim = insert_bit(dg, p, 1 - cbit);
        const float xv = g_z[(row0 + m2) * DIMS + tdim];

        float ww[BINS], hh[BINS], dd[BINS + 1];

        float mx = pr[0];
        #pragma unroll
        for (int i = 1; i < BINS; i++) mx = fmaxf(mx, pr[i]);
        float ssum = 0.f;
        #pragma unroll
        for (int i = 0; i < BINS; i++) { ww[i] = expf(pr[i] - mx); ssum += ww[i]; }
        float sc = (1.0f - MIN_W * (float)BINS) / ssum;
        #pragma unroll
        for (int i = 0; i < BINS; i++) ww[i] = MIN_W + ww[i] * sc;

        mx = pr[BINS];
        #pragma unroll
        for (int i = 1; i < BINS; i++) mx = fmaxf(mx, pr[BINS + i]);
        ssum = 0.f;
        #pragma unroll
        for (int i = 0; i < BINS; i++) { hh[i] = expf(pr[BINS + i] - mx); ssum += hh[i]; }
        sc = (1.0f - MIN_H * (float)BINS) / ssum;
        #pragma unroll
        for (int i = 0; i < BINS; i++) hh[i] = MIN_H + hh[i] * sc;

        #pragma unroll
        for (int i = 0; i <= BINS; i++) {
            float u = pr[2 * BINS + i];
            dd[i] = MIN_D + (fmaxf(u, 0.f) + log1pf(expf(-fabsf(u))));
        }

        float cw[BINS + 1], ch[BINS + 1];
        cw[0] = 0.f; ch[0] = 0.f;
        #pragma unroll
        for (int i = 1; i <= BINS; i++) { cw[i] = cw[i-1] + ww[i-1]; ch[i] = ch[i-1] + hh[i-1]; }

        int cnt = 0;
        #pragma unroll
        for (int i = 0; i <= BINS; i++) cnt += (xv >= cw[i]) ? 1 : 0;
        int idx = cnt - 1;
        idx = idx < 0 ? 0 : (idx > BINS - 1 ? BINS - 1 : idx);

        float xk = 0.f, wk = 1.f, yk = 0.f, hk = 1.f, dk = 1.f, dk1 = 1.f;
        #pragma unroll
        for (int i = 0; i < BINS; i++) {
            if (i == idx) { xk = cw[i]; wk = ww[i]; yk = ch[i]; hk = hh[i]; dk = dd[i]; dk1 = dd[i+1]; }
        }

        float th  = fminf(fmaxf((xv - xk) / wk, 0.f), 1.f);
        float sr  = hk / wk;
        float t1  = th * (1.f - th);
        float den = sr + (dk1 + dk - 2.f * sr) * t1;
        float y   = yk + hk * (sr * th * th + dk * t1) / den;
        float omt = 1.f - th;
        float ld  = 2.f * logf(sr)
                  + logf(dk1 * th * th + 2.f * sr * t1 + dk * omt * omt)
                  - 2.f * logf(den);

        g_z[(row0 + m2) * DIMS + tdim] = y;

        #pragma unroll
        for (int off = 4; off > 0; off >>= 1)
            ld += __shfl_down_sync(0xffffffffu, ld, off);
        if (dg == 0) out[row0 + m2] += ld;
    }
}

extern "C" void kernel_launch(void* const* d_in, const int* in_sizes, int n_in,
                              void* d_out, int out_size) {
    const float* x  = (const float*)d_in[0];
    const float* c  = (const float*)d_in[1];
    const float* W0 = (const float*)d_in[2];
    const float* b0 = (const float*)d_in[3];
    const float* W1 = (const float*)d_in[4];
    const float* b1 = (const float*)d_in[5];
    const float* W2 = (const float*)d_in[6];
    const float* b2 = (const float*)d_in[7];
    float* out = (float*)d_out;

    size_t smem = (size_t)SMEM_FLOATS * sizeof(float);
    cudaFuncSetAttribute(flow_block_kernel,
                         cudaFuncAttributeMaxDynamicSharedMemorySize, (int)smem);

    init_kernel<<<(N_SAMPLES * DIMS + 255) / 256, 256>>>(x, out);

    for (int b = 0; b < NBLOCKS; b++) {
        flow_block_kernel<<<N_SAMPLES / MT, NTHREADS, smem>>>(
            b, c,
            W0 + (size_t)b * FEAT_IN * UNITS,
            b0 + (size_t)b * UNITS,
            W1 + (size_t)b * UNITS * UNITS,
            b1 + (size_t)b * UNITS,
            W2 + (size_t)b * UNITS * FEAT_OUT,
            b2 + (size_t)b * FEAT_OUT,
            out);
    }
}

// round 6
// speedup vs baseline: 16.6685x; 2.0356x over previous
#include <cuda_runtime.h>
#include <cuda_bf16.h>
#include <math.h>
#include <stdint.h>

#define NS       131072
#define DIMS     16
#define DIMSC    16
#define UNITS    512
#define BINS     10
#define DT       8
#define FEAT_IN  24
#define FEAT_OUT 248
#define NBLOCKS  8
#define MIN_W    0.001f
#define MIN_H    0.001f
#define MIN_D    0.001f

#define MTS      64
#define NTHREADS 512

// activation rows padded to 520 bf16 (1040 B, odd multiple of 16B -> conflict-free ldmatrix)
#define PADH     520
#define PADW     520
#define PADW2    264

// g_img per-flow-block layout (bytes):
//  L0: 2 chunks x 33280   (chunk = 16 k-rows: hi plane 16640 + lo plane 16640)
//  L1: 32 chunks x 33280
//  L2: 16 chunks x 33792  (chunk = 32 k-rows: hi 16896 + lo 16896)
#define L0_OFF   0
#define L1_OFF   66560
#define L2_OFF   1131520
#define BLK_BYTES 1672192

// smem byte offsets
#define OFF_AH   0         // activation hi [64 x 520] bf16 = 66560 (also fp32 park 64x260)
#define OFF_AL   66560     // activation lo
#define OFF_W    133120    // 2 weight buffers x 33792
#define OFF_IH   200704    // input tile hi [64 x 40] bf16 = 5120
#define OFF_IL   205824
#define SMEM_TOTAL 210944

__device__ float g_z[NS * DIMS];
__device__ __align__(16) uint8_t g_img[(size_t)NBLOCKS * BLK_BYTES];

__device__ __forceinline__ uint32_t smem_u32(const void* p) {
    return (uint32_t)__cvta_generic_to_shared(p);
}
#define CP16(s, g)  asm volatile("cp.async.cg.shared.global [%0], [%1], 16;" :: "r"(s), "l"(g))
#define CPCOMMIT()  asm volatile("cp.async.commit_group;")
#define CPWAIT1()   asm volatile("cp.async.wait_group 1;" ::: "memory")
#define CPWAIT0()   asm volatile("cp.async.wait_group 0;" ::: "memory")

__device__ __forceinline__ void ldm4(uint32_t* r, uint32_t a) {
    asm volatile("ldmatrix.sync.aligned.m8n8.x4.shared.b16 {%0,%1,%2,%3}, [%4];"
        : "=r"(r[0]), "=r"(r[1]), "=r"(r[2]), "=r"(r[3]) : "r"(a));
}
__device__ __forceinline__ void ldm4t(uint32_t* r, uint32_t a) {
    asm volatile("ldmatrix.sync.aligned.m8n8.x4.trans.shared.b16 {%0,%1,%2,%3}, [%4];"
        : "=r"(r[0]), "=r"(r[1]), "=r"(r[2]), "=r"(r[3]) : "r"(a));
}
__device__ __forceinline__ void mma16816(float* d, const uint32_t* a, uint32_t b0, uint32_t b1) {
    asm volatile("mma.sync.aligned.m16n8k16.row.col.f32.bf16.bf16.f32 "
        "{%0,%1,%2,%3}, {%4,%5,%6,%7}, {%8,%9}, {%0,%1,%2,%3};"
        : "+f"(d[0]), "+f"(d[1]), "+f"(d[2]), "+f"(d[3])
        : "r"(a[0]), "r"(a[1]), "r"(a[2]), "r"(a[3]), "r"(b0), "r"(b1));
}
__device__ __forceinline__ int insert_bit(int f, int p, int bit) {
    int lo = f & ((1 << p) - 1);
    int hi = f >> p;
    return (hi << (p + 1)) | (bit << p) | lo;
}

// ---------------- init ----------------
__global__ void init_kernel(const float* __restrict__ x, float* __restrict__ out) {
    int i = blockIdx.x * blockDim.x + threadIdx.x;
    if (i < NS * DIMS) g_z[i] = x[i];
    if (i < NS) out[i] = 0.f;
}

// ---------------- weight image prep: bf16 hi/lo planes, padded rows ----------------
__global__ void prep_kernel(const float* __restrict__ W0,
                            const float* __restrict__ W1,
                            const float* __restrict__ W2) {
    int plane = blockIdx.x;
    int b = plane / 100, r = plane % 100;
    uint8_t* gb = g_img + (size_t)b * BLK_BYTES;
    int layer, chunk, half;
    if (r < 4)       { layer = 0; chunk = r >> 1;        half = r & 1; }
    else if (r < 68) { int q = r - 4;  layer = 1; chunk = q >> 1; half = q & 1; }
    else             { int q = r - 68; layer = 2; chunk = q >> 1; half = q & 1; }

    int rows  = (layer == 2) ? 32 : 16;
    int padc  = (layer == 2) ? PADW2 : PADW;
    int ncols = (layer == 2) ? FEAT_OUT : UNITS;
    uint8_t* dst;
    if (layer == 0)      dst = gb + L0_OFF + chunk * 33280 + half * 16640;
    else if (layer == 1) dst = gb + L1_OFF + chunk * 33280 + half * 16640;
    else                 dst = gb + L2_OFF + chunk * 33792 + half * 16896;
    __nv_bfloat16* d16 = (__nv_bfloat16*)dst;

    for (int i = threadIdx.x; i < rows * padc; i += blockDim.x) {
        int row = i / padc, col = i % padc;
        int k = chunk * rows + row;
        float w = 0.f;
        if (col < ncols) {
            if (layer == 0)      { if (k < FEAT_IN) w = W0[((size_t)b * FEAT_IN + k) * UNITS + col]; }
            else if (layer == 1) { w = W1[((size_t)b * UNITS + k) * UNITS + col]; }
            else                 { w = W2[((size_t)b * UNITS + k) * FEAT_OUT + col]; }
        }
        float hi = __bfloat162float(__float2bfloat16(w));
        float v = half ? (w - hi) : w;
        d16[i] = __float2bfloat16(v);
    }
}

// ---------------- helpers ----------------
__device__ __forceinline__ void copy16(uint32_t sdst, const uint8_t* g, int n16, int tid) {
    for (int i = tid; i < n16; i += NTHREADS)
        CP16(sdst + i * 16, g + (size_t)i * 16);
}

// epilogue for L0/L1: bias+relu, split hi/lo, store into activation tile (16 n8-tiles)
__device__ __forceinline__ void epi_h(float* acc /*64*/, const float* __restrict__ bias,
                                      uint8_t* sm, int mw, int nw, int lane) {
    int r0 = mw * 16 + (lane >> 2);
    int c0 = (lane & 3) * 2;
    uint8_t* AH = sm + OFF_AH;
    uint8_t* AL = sm + OFF_AL;
    #pragma unroll
    for (int t = 0; t < 16; t++) {
        int col = nw * 128 + t * 8 + c0;
        float bx = bias[col], by = bias[col + 1];
        #pragma unroll
        for (int rr = 0; rr < 2; rr++) {
            float vx = fmaxf(acc[t * 4 + rr * 2 + 0] + bx, 0.f);
            float vy = fmaxf(acc[t * 4 + rr * 2 + 1] + by, 0.f);
            __nv_bfloat16 hx = __float2bfloat16(vx);
            __nv_bfloat16 hy = __float2bfloat16(vy);
            __nv_bfloat16 lx = __float2bfloat16(vx - __bfloat162float(hx));
            __nv_bfloat16 ly = __float2bfloat16(vy - __bfloat162float(hy));
            int row = r0 + rr * 8;
            uint32_t off = (uint32_t)(row * PADH + col) * 2;
            *(__nv_bfloat162*)(AH + off) = __halves2bfloat162(hx, hy);
            *(__nv_bfloat162*)(AL + off) = __halves2bfloat162(lx, ly);
        }
    }
}

// ---------------- main fused flow-block kernel ----------------
__global__ void __launch_bounds__(NTHREADS, 1)
flow_block_kernel(int blk,
                  const float* __restrict__ cc,
                  const float* __restrict__ B0, const float* __restrict__ B1,
                  const float* __restrict__ B2,
                  float* __restrict__ out)
{
    extern __shared__ __align__(128) uint8_t sm[];
    const uint32_t s0 = smem_u32(sm);
    const int tid  = threadIdx.x;
    const int wid  = tid >> 5;
    const int lane = tid & 31;
    const int mw   = wid & 3;     // sample group (16 rows)
    const int nw   = wid >> 2;    // column group (128 cols for L0/L1, 64 for L2)
    const int row0 = blockIdx.x * MTS;
    const int p    = blk >> 1;
    const int cbit = 1 - (blk & 1);
    const uint8_t* gb = g_img + (size_t)blk * BLK_BYTES;

    const int l15  = lane & 15;
    const int lhi  = lane >> 4;
    const int arow = mw * 16 + l15;
    const uint32_t aoffA = (uint32_t)(arow * (PADH * 2)) + lhi * 16;
    const uint32_t aoffI = (uint32_t)(arow * 80)         + lhi * 16;
    const int krow = (lane & 7) + ((lane >> 3) & 1) * 8;
    const uint32_t woff1 = (uint32_t)(krow * (PADW * 2))  + (uint32_t)lhi * 16;
    const uint32_t woff2 = (uint32_t)(krow * (PADW2 * 2)) + (uint32_t)lhi * 16;

    // ---- stage L0 weights (both chunks) ----
    copy16(s0 + OFF_W, gb + L0_OFF, 4160, tid);
    CPCOMMIT();

    // ---- build input tile [64 x 32] hi/lo, zero-padded ----
    for (int i = tid; i < 1280; i += NTHREADS) {
        ((uint32_t*)(sm + OFF_IH))[i] = 0u;
        ((uint32_t*)(sm + OFF_IL))[i] = 0u;
    }
    __syncthreads();
    for (int i = tid; i < MTS * FEAT_IN; i += NTHREADS) {
        int m = i / FEAT_IN, f = i % FEAT_IN;
        float v = (f < DT) ? g_z[(row0 + m) * DIMS + insert_bit(f, p, cbit)]
                           : cc[(row0 + m) * DIMSC + (f - DT)];
        __nv_bfloat16 hi = __float2bfloat16(v);
        __nv_bfloat16 lo = __float2bfloat16(v - __bfloat162float(hi));
        ((__nv_bfloat16*)(sm + OFF_IH))[m * 40 + f] = hi;
        ((__nv_bfloat16*)(sm + OFF_IL))[m * 40 + f] = lo;
    }
    CPWAIT0();
    __syncthreads();

    float acc[64];
    #pragma unroll
    for (int i = 0; i < 64; i++) acc[i] = 0.f;

    // ---- L0: 2 ksteps, FULL 128 cols/warp (np < 8) ----
    #pragma unroll
    for (int ks = 0; ks < 2; ks++) {
        uint32_t ah[4], al[4];
        ldm4(ah, s0 + OFF_IH + aoffI + ks * 32);
        ldm4(al, s0 + OFF_IL + aoffI + ks * 32);
        uint32_t wb = s0 + OFF_W + ks * 33280;
        #pragma unroll
        for (int np = 0; np < 8; np++) {
            uint32_t bh[4], bl[4];
            uint32_t ba = wb + woff1 + (uint32_t)(nw * 128 + np * 16) * 2;
            ldm4t(bh, ba);
            ldm4t(bl, ba + 16640);
            float* d0 = acc + (2 * np) * 4;
            float* d1 = acc + (2 * np + 1) * 4;
            mma16816(d0, ah, bh[0], bh[1]);
            mma16816(d0, ah, bl[0], bl[1]);
            mma16816(d0, al, bh[0], bh[1]);
            mma16816(d1, ah, bh[2], bh[3]);
            mma16816(d1, ah, bl[2], bl[3]);
            mma16816(d1, al, bh[2], bh[3]);
        }
    }
    __syncthreads();

    // ---- L1 prologue: chunk 0, then epilogue0 overlapped ----
    copy16(s0 + OFF_W, gb + L1_OFF, 2080, tid);
    CPCOMMIT();
    epi_h(acc, B0, sm, mw, nw, lane);
    #pragma unroll
    for (int i = 0; i < 64; i++) acc[i] = 0.f;

    // ---- L1: 32 k-chunks streamed, FULL 128 cols/warp (np < 8) ----
    for (int c = 0; c < 32; c++) {
        if (c + 1 < 32) {
            copy16(s0 + OFF_W + ((c + 1) & 1) * 33792, gb + L1_OFF + (size_t)(c + 1) * 33280, 2080, tid);
            CPCOMMIT();
            CPWAIT1();
        } else {
            CPWAIT0();
        }
        __syncthreads();
        uint32_t ah[4], al[4];
        ldm4(ah, s0 + OFF_AH + aoffA + c * 32);
        ldm4(al, s0 + OFF_AL + aoffA + c * 32);
        uint32_t wb = s0 + OFF_W + (c & 1) * 33792;
        #pragma unroll
        for (int np = 0; np < 8; np++) {
            uint32_t bh[4], bl[4];
            uint32_t ba = wb + woff1 + (uint32_t)(nw * 128 + np * 16) * 2;
            ldm4t(bh, ba);
            ldm4t(bl, ba + 16640);
            float* d0 = acc + (2 * np) * 4;
            float* d1 = acc + (2 * np + 1) * 4;
            mma16816(d0, ah, bh[0], bh[1]);
            mma16816(d0, ah, bl[0], bl[1]);
            mma16816(d0, al, bh[0], bh[1]);
            mma16816(d1, ah, bh[2], bh[3]);
            mma16816(d1, ah, bl[2], bl[3]);
            mma16816(d1, al, bh[2], bh[3]);
        }
        __syncthreads();
    }

    // ---- L2 prologue + epilogue1 ----
    copy16(s0 + OFF_W, gb + L2_OFF, 2112, tid);
    CPCOMMIT();
    epi_h(acc, B1, sm, mw, nw, lane);

    float acc2[32];
    #pragma unroll
    for (int i = 0; i < 32; i++) acc2[i] = 0.f;

    // ---- L2: 16 chunks (32 k-rows each), 64 cols/warp (np < 4 is complete here) ----
    for (int c = 0; c < 16; c++) {
        if (c + 1 < 16) {
            copy16(s0 + OFF_W + ((c + 1) & 1) * 33792, gb + L2_OFF + (size_t)(c + 1) * 33792, 2112, tid);
            CPCOMMIT();
            CPWAIT1();
        } else {
            CPWAIT0();
        }
        __syncthreads();
        uint32_t wb = s0 + OFF_W + (c & 1) * 33792;
        #pragma unroll
        for (int ks = 0; ks < 2; ks++) {
            uint32_t ah[4], al[4];
            ldm4(ah, s0 + OFF_AH + aoffA + c * 64 + ks * 32);
            ldm4(al, s0 + OFF_AL + aoffA + c * 64 + ks * 32);
            #pragma unroll
            for (int np = 0; np < 4; np++) {
                uint32_t bh[4], bl[4];
                uint32_t ba = wb + (uint32_t)(ks * 16 * PADW2 * 2) + woff2
                            + (uint32_t)(nw * 64 + np * 16) * 2;
                ldm4t(bh, ba);
                ldm4t(bl, ba + 16896);
                float* d0 = acc2 + (2 * np) * 4;
                float* d1 = acc2 + (2 * np + 1) * 4;
                mma16816(d0, ah, bh[0], bh[1]);
                mma16816(d0, ah, bl[0], bl[1]);
                mma16816(d0, al, bh[0], bh[1]);
                mma16816(d1, ah, bh[2], bh[3]);
                mma16816(d1, ah, bl[2], bl[3]);
                mma16816(d1, al, bh[2], bh[3]);
            }
        }
        __syncthreads();
    }

    // ---- park params fp32 into AH region (h dead) ----
    float* park = (float*)(sm + OFF_AH);
    {
        int r0 = mw * 16 + (lane >> 2);
        int c0 = (lane & 3) * 2;
        #pragma unroll
        for (int t = 0; t < 8; t++) {
            int col = nw * 64 + t * 8 + c0;
            *(float2*)(park + r0 * 260 + col)       = make_float2(acc2[t * 4 + 0], acc2[t * 4 + 1]);
            *(float2*)(park + (r0 + 8) * 260 + col) = make_float2(acc2[t * 4 + 2], acc2[t * 4 + 3]);
        }
    }
    __syncthreads();

    // ---- spline + logdet ----
    {
        const int m2 = tid >> 3;
        const int dg = tid & 7;
        float pr[31];
        #pragma unroll
        for (int j = 0; j < 31; j++)
            pr[j] = park[m2 * 260 + dg * 31 + j] + B2[dg * 31 + j];

        const int tdim = insert_bit(dg, p, 1 - cbit);
        const float xv = g_z[(row0 + m2) * DIMS + tdim];

        float ww[BINS], hh[BINS], dd[BINS + 1];
        float mx = pr[0];
        #pragma unroll
        for (int i = 1; i < BINS; i++) mx = fmaxf(mx, pr[i]);
        float ssum = 0.f;
        #pragma unroll
        for (int i = 0; i < BINS; i++) { ww[i] = expf(pr[i] - mx); ssum += ww[i]; }
        float sc = (1.0f - MIN_W * (float)BINS) / ssum;
        #pragma unroll
        for (int i = 0; i < BINS; i++) ww[i] = MIN_W + ww[i] * sc;

        mx = pr[BINS];
        #pragma unroll
        for (int i = 1; i < BINS; i++) mx = fmaxf(mx, pr[BINS + i]);
        ssum = 0.f;
        #pragma unroll
        for (int i = 0; i < BINS; i++) { hh[i] = expf(pr[BINS + i] - mx); ssum += hh[i]; }
        sc = (1.0f - MIN_H * (float)BINS) / ssum;
        #pragma unroll
        for (int i = 0; i < BINS; i++) hh[i] = MIN_H + hh[i] * sc;

        #pragma unroll
        for (int i = 0; i <= BINS; i++) {
            float u = pr[2 * BINS + i];
            dd[i] = MIN_D + (fmaxf(u, 0.f) + log1pf(expf(-fabsf(u))));
        }

        float cw[BINS + 1], ch[BINS + 1];
        cw[0] = 0.f; ch[0] = 0.f;
        #pragma unroll
        for (int i = 1; i <= BINS; i++) { cw[i] = cw[i-1] + ww[i-1]; ch[i] = ch[i-1] + hh[i-1]; }

        int cnt = 0;
        #pragma unroll
        for (int i = 0; i <= BINS; i++) cnt += (xv >= cw[i]) ? 1 : 0;
        int idx = cnt - 1;
        idx = idx < 0 ? 0 : (idx > BINS - 1 ? BINS - 1 : idx);

        float xk = 0.f, wk = 1.f, yk = 0.f, hk = 1.f, dk = 1.f, dk1 = 1.f;
        #pragma unroll
        for (int i = 0; i < BINS; i++)
            if (i == idx) { xk = cw[i]; wk = ww[i]; yk = ch[i]; hk = hh[i]; dk = dd[i]; dk1 = dd[i+1]; }

        float th  = fminf(fmaxf((xv - xk) / wk, 0.f), 1.f);
        float sr  = hk / wk;
        float t1  = th * (1.f - th);
        float den = sr + (dk1 + dk - 2.f * sr) * t1;
        float y   = yk + hk * (sr * th * th + dk * t1) / den;
        float omt = 1.f - th;
        float ld  = 2.f * logf(sr)
                  + logf(dk1 * th * th + 2.f * sr * t1 + dk * omt * omt)
                  - 2.f * logf(den);

        g_z[(row0 + m2) * DIMS + tdim] = y;

        #pragma unroll
        for (int off = 4; off > 0; off >>= 1)
            ld += __shfl_down_sync(0xffffffffu, ld, off);
        if (dg == 0) out[row0 + m2] += ld;
    }
}

extern "C" void kernel_launch(void* const* d_in, const int* in_sizes, int n_in,
                              void* d_out, int out_size) {
    const float* x  = (const float*)d_in[0];
    const float* c  = (const float*)d_in[1];
    const float* W0 = (const float*)d_in[2];
    const float* b0 = (const float*)d_in[3];
    const float* W1 = (const float*)d_in[4];
    const float* b1 = (const float*)d_in[5];
    const float* W2 = (const float*)d_in[6];
    const float* b2 = (const float*)d_in[7];
    float* out = (float*)d_out;

    cudaFuncSetAttribute(flow_block_kernel,
                         cudaFuncAttributeMaxDynamicSharedMemorySize, SMEM_TOTAL);

    init_kernel<<<(NS * DIMS + 255) / 256, 256>>>(x, out);
    prep_kernel<<<NBLOCKS * 100, 256>>>(W0, W1, W2);

    for (int b = 0; b < NBLOCKS; b++) {
        flow_block_kernel<<<NS / MTS, NTHREADS, SMEM_TOTAL>>>(
            b, c,
            b0 + (size_t)b * UNITS,
            b1 + (size_t)b * UNITS,
            b2 + (size_t)b * FEAT_OUT,
            out);
    }
}

// round 7
// speedup vs baseline: 20.0054x; 1.2002x over previous
#include <cuda_runtime.h>
#include <cuda_fp16.h>
#include <math.h>
#include <stdint.h>

#define NS       131072
#define DIMS     16
#define DIMSC    16
#define UNITS    512
#define BINS     10
#define DT       8
#define FEAT_IN  24
#define FEAT_OUT 248
#define NBLOCKS  8
#define MIN_W    0.001f
#define MIN_H    0.001f
#define MIN_D    0.001f

#define MTS      64
#define NTHREADS 512

// activation rows padded to 520 fp16 (1040 B, odd multiple of 16B -> conflict-free ldmatrix)
#define PADH     520
#define PADW     520
#define PADW2    264

// g_img per-flow-block layout (bytes):
//  L0: 2 chunks x 33280   (chunk = 16 k-rows: hi plane 16640 + lo plane 16640)
//  L1: 32 chunks x 33280
//  L2: 16 chunks x 33792  (chunk = 32 k-rows: hi 16896 + lo 16896)
#define L0_OFF   0
#define L1_OFF   66560
#define L2_OFF   1131520
#define BLK_BYTES 1672192

// smem byte offsets
#define OFF_AH   0         // activation [64 x 520] fp16 = 66560 (also fp32 park 64x260)
#define OFF_W    66560     // 2 weight buffers x 33792 = 67584
#define OFF_IH   134144    // input tile [64 x 40] fp16 = 5120
#define SMEM_TOTAL 139264

__device__ float g_z[NS * DIMS];
__device__ __align__(16) uint8_t g_img[(size_t)NBLOCKS * BLK_BYTES];

__device__ __forceinline__ uint32_t smem_u32(const void* p) {
    return (uint32_t)__cvta_generic_to_shared(p);
}
#define CP16(s, g)  asm volatile("cp.async.cg.shared.global [%0], [%1], 16;" :: "r"(s), "l"(g))
#define CPCOMMIT()  asm volatile("cp.async.commit_group;")
#define CPWAIT1()   asm volatile("cp.async.wait_group 1;" ::: "memory")
#define CPWAIT0()   asm volatile("cp.async.wait_group 0;" ::: "memory")

__device__ __forceinline__ void ldm4(uint32_t* r, uint32_t a) {
    asm volatile("ldmatrix.sync.aligned.m8n8.x4.shared.b16 {%0,%1,%2,%3}, [%4];"
        : "=r"(r[0]), "=r"(r[1]), "=r"(r[2]), "=r"(r[3]) : "r"(a));
}
__device__ __forceinline__ void ldm4t(uint32_t* r, uint32_t a) {
    asm volatile("ldmatrix.sync.aligned.m8n8.x4.trans.shared.b16 {%0,%1,%2,%3}, [%4];"
        : "=r"(r[0]), "=r"(r[1]), "=r"(r[2]), "=r"(r[3]) : "r"(a));
}
__device__ __forceinline__ void mma16816(float* d, const uint32_t* a, uint32_t b0, uint32_t b1) {
    asm volatile("mma.sync.aligned.m16n8k16.row.col.f32.f16.f16.f32 "
        "{%0,%1,%2,%3}, {%4,%5,%6,%7}, {%8,%9}, {%0,%1,%2,%3};"
        : "+f"(d[0]), "+f"(d[1]), "+f"(d[2]), "+f"(d[3])
        : "r"(a[0]), "r"(a[1]), "r"(a[2]), "r"(a[3]), "r"(b0), "r"(b1));
}
__device__ __forceinline__ int insert_bit(int f, int p, int bit) {
    int lo = f & ((1 << p) - 1);
    int hi = f >> p;
    return (hi << (p + 1)) | (bit << p) | lo;
}

// ---------------- init ----------------
__global__ void init_kernel(const float* __restrict__ x, float* __restrict__ out) {
    int i = blockIdx.x * blockDim.x + threadIdx.x;
    if (i < NS * DIMS) g_z[i] = x[i];
    if (i < NS) out[i] = 0.f;
}

// ---------------- weight image prep: fp16 hi/lo planes, padded rows ----------------
__global__ void prep_kernel(const float* __restrict__ W0,
                            const float* __restrict__ W1,
                            const float* __restrict__ W2) {
    int plane = blockIdx.x;
    int b = plane / 100, r = plane % 100;
    uint8_t* gb = g_img + (size_t)b * BLK_BYTES;
    int layer, chunk, half;
    if (r < 4)       { layer = 0; chunk = r >> 1;        half = r & 1; }
    else if (r < 68) { int q = r - 4;  layer = 1; chunk = q >> 1; half = q & 1; }
    else             { int q = r - 68; layer = 2; chunk = q >> 1; half = q & 1; }

    int rows  = (layer == 2) ? 32 : 16;
    int padc  = (layer == 2) ? PADW2 : PADW;
    int ncols = (layer == 2) ? FEAT_OUT : UNITS;
    uint8_t* dst;
    if (layer == 0)      dst = gb + L0_OFF + chunk * 33280 + half * 16640;
    else if (layer == 1) dst = gb + L1_OFF + chunk * 33280 + half * 16640;
    else                 dst = gb + L2_OFF + chunk * 33792 + half * 16896;
    __half* d16 = (__half*)dst;

    for (int i = threadIdx.x; i < rows * padc; i += blockDim.x) {
        int row = i / padc, col = i % padc;
        int k = chunk * rows + row;
        float w = 0.f;
        if (col < ncols) {
            if (layer == 0)      { if (k < FEAT_IN) w = W0[((size_t)b * FEAT_IN + k) * UNITS + col]; }
            else if (layer == 1) { w = W1[((size_t)b * UNITS + k) * UNITS + col]; }
            else                 { w = W2[((size_t)b * UNITS + k) * FEAT_OUT + col]; }
        }
        __half hi = __float2half(w);
        float v = half ? (w - __half2float(hi)) : w;
        d16[i] = __float2half(v);
    }
}

// ---------------- helpers ----------------
__device__ __forceinline__ void copy16(uint32_t sdst, const uint8_t* g, int n16, int tid) {
    for (int i = tid; i < n16; i += NTHREADS)
        CP16(sdst + i * 16, g + (size_t)i * 16);
}

// epilogue for L0/L1: bias+relu, store fp16 into activation tile (16 n8-tiles)
__device__ __forceinline__ void epi_h(float* acc /*64*/, const float* __restrict__ bias,
                                      uint8_t* sm, int mw, int nw, int lane) {
    int r0 = mw * 16 + (lane >> 2);
    int c0 = (lane & 3) * 2;
    uint8_t* AH = sm + OFF_AH;
    #pragma unroll
    for (int t = 0; t < 16; t++) {
        int col = nw * 128 + t * 8 + c0;
        float bx = bias[col], by = bias[col + 1];
        #pragma unroll
        for (int rr = 0; rr < 2; rr++) {
            float vx = fmaxf(acc[t * 4 + rr * 2 + 0] + bx, 0.f);
            float vy = fmaxf(acc[t * 4 + rr * 2 + 1] + by, 0.f);
            int row = r0 + rr * 8;
            uint32_t off = (uint32_t)(row * PADH + col) * 2;
            *(__half2*)(AH + off) = __halves2half2(__float2half(vx), __float2half(vy));
        }
    }
}

// ---------------- main fused flow-block kernel ----------------
__global__ void __launch_bounds__(NTHREADS, 1)
flow_block_kernel(int blk,
                  const float* __restrict__ cc,
                  const float* __restrict__ B0, const float* __restrict__ B1,
                  const float* __restrict__ B2,
                  float* __restrict__ out)
{
    extern __shared__ __align__(128) uint8_t sm[];
    const uint32_t s0 = smem_u32(sm);
    const int tid  = threadIdx.x;
    const int wid  = tid >> 5;
    const int lane = tid & 31;
    const int mw   = wid & 3;     // sample group (16 rows)
    const int nw   = wid >> 2;    // column group (128 cols for L0/L1, 64 for L2)
    const int row0 = blockIdx.x * MTS;
    const int p    = blk >> 1;
    const int cbit = 1 - (blk & 1);
    const uint8_t* gb = g_img + (size_t)blk * BLK_BYTES;

    const int l15  = lane & 15;
    const int lhi  = lane >> 4;
    const int arow = mw * 16 + l15;
    const uint32_t aoffA = (uint32_t)(arow * (PADH * 2)) + lhi * 16;
    const uint32_t aoffI = (uint32_t)(arow * 80)         + lhi * 16;
    const int krow = (lane & 7) + ((lane >> 3) & 1) * 8;
    const uint32_t woff1 = (uint32_t)(krow * (PADW * 2))  + (uint32_t)lhi * 16;
    const uint32_t woff2 = (uint32_t)(krow * (PADW2 * 2)) + (uint32_t)lhi * 16;

    // ---- stage L0 weights (both chunks) ----
    copy16(s0 + OFF_W, gb + L0_OFF, 4160, tid);
    CPCOMMIT();

    // ---- build input tile [64 x 32] fp16, zero-padded ----
    for (int i = tid; i < 1280; i += NTHREADS)
        ((uint32_t*)(sm + OFF_IH))[i] = 0u;
    __syncthreads();
    for (int i = tid; i < MTS * FEAT_IN; i += NTHREADS) {
        int m = i / FEAT_IN, f = i % FEAT_IN;
        float v = (f < DT) ? g_z[(row0 + m) * DIMS + insert_bit(f, p, cbit)]
                           : cc[(row0 + m) * DIMSC + (f - DT)];
        ((__half*)(sm + OFF_IH))[m * 40 + f] = __float2half(v);
    }
    CPWAIT0();
    __syncthreads();

    float acc[64];
    #pragma unroll
    for (int i = 0; i < 64; i++) acc[i] = 0.f;

    // ---- L0: 2 ksteps, 128 cols/warp ----
    #pragma unroll
    for (int ks = 0; ks < 2; ks++) {
        uint32_t ah[4];
        ldm4(ah, s0 + OFF_IH + aoffI + ks * 32);
        uint32_t wb = s0 + OFF_W + ks * 33280;
        #pragma unroll
        for (int np = 0; np < 8; np++) {
            uint32_t bh[4], bl[4];
            uint32_t ba = wb + woff1 + (uint32_t)(nw * 128 + np * 16) * 2;
            ldm4t(bh, ba);
            ldm4t(bl, ba + 16640);
            float* d0 = acc + (2 * np) * 4;
            float* d1 = acc + (2 * np + 1) * 4;
            mma16816(d0, ah, bh[0], bh[1]);
            mma16816(d0, ah, bl[0], bl[1]);
            mma16816(d1, ah, bh[2], bh[3]);
            mma16816(d1, ah, bl[2], bl[3]);
        }
    }
    __syncthreads();

    // ---- L1 prologue: chunk 0, then epilogue0 overlapped ----
    copy16(s0 + OFF_W, gb + L1_OFF, 2080, tid);
    CPCOMMIT();
    epi_h(acc, B0, sm, mw, nw, lane);
    #pragma unroll
    for (int i = 0; i < 64; i++) acc[i] = 0.f;

    // ---- L1: 32 k-chunks streamed, 128 cols/warp ----
    for (int c = 0; c < 32; c++) {
        if (c + 1 < 32) {
            copy16(s0 + OFF_W + ((c + 1) & 1) * 33792, gb + L1_OFF + (size_t)(c + 1) * 33280, 2080, tid);
            CPCOMMIT();
            CPWAIT1();
        } else {
            CPWAIT0();
        }
        __syncthreads();
        uint32_t ah[4];
        ldm4(ah, s0 + OFF_AH + aoffA + c * 32);
        uint32_t wb = s0 + OFF_W + (c & 1) * 33792;
        #pragma unroll
        for (int np = 0; np < 8; np++) {
            uint32_t bh[4], bl[4];
            uint32_t ba = wb + woff1 + (uint32_t)(nw * 128 + np * 16) * 2;
            ldm4t(bh, ba);
            ldm4t(bl, ba + 16640);
            float* d0 = acc + (2 * np) * 4;
            float* d1 = acc + (2 * np + 1) * 4;
            mma16816(d0, ah, bh[0], bh[1]);
            mma16816(d0, ah, bl[0], bl[1]);
            mma16816(d1, ah, bh[2], bh[3]);
            mma16816(d1, ah, bl[2], bl[3]);
        }
        __syncthreads();
    }

    // ---- L2 prologue + epilogue1 ----
    copy16(s0 + OFF_W, gb + L2_OFF, 2112, tid);
    CPCOMMIT();
    epi_h(acc, B1, sm, mw, nw, lane);

    float acc2[32];
    #pragma unroll
    for (int i = 0; i < 32; i++) acc2[i] = 0.f;

    // ---- L2: 16 chunks (32 k-rows each), 64 cols/warp ----
    for (int c = 0; c < 16; c++) {
        if (c + 1 < 16) {
            copy16(s0 + OFF_W + ((c + 1) & 1) * 33792, gb + L2_OFF + (size_t)(c + 1) * 33792, 2112, tid);
            CPCOMMIT();
            CPWAIT1();
        } else {
            CPWAIT0();
        }
        __syncthreads();
        uint32_t wb = s0 + OFF_W + (c & 1) * 33792;
        #pragma unroll
        for (int ks = 0; ks < 2; ks++) {
            uint32_t ah[4];
            ldm4(ah, s0 + OFF_AH + aoffA + c * 64 + ks * 32);
            #pragma unroll
            for (int np = 0; np < 4; np++) {
                uint32_t bh[4], bl[4];
                uint32_t ba = wb + (uint32_t)(ks * 16 * PADW2 * 2) + woff2
                            + (uint32_t)(nw * 64 + np * 16) * 2;
                ldm4t(bh, ba);
                ldm4t(bl, ba + 16896);
                float* d0 = acc2 + (2 * np) * 4;
                float* d1 = acc2 + (2 * np + 1) * 4;
                mma16816(d0, ah, bh[0], bh[1]);
                mma16816(d0, ah, bl[0], bl[1]);
                mma16816(d1, ah, bh[2], bh[3]);
                mma16816(d1, ah, bl[2], bl[3]);
            }
        }
        __syncthreads();
    }

    // ---- park params fp32 into AH region (h dead) ----
    float* park = (float*)(sm + OFF_AH);
    {
        int r0 = mw * 16 + (lane >> 2);
        int c0 = (lane & 3) * 2;
        #pragma unroll
        for (int t = 0; t < 8; t++) {
            int col = nw * 64 + t * 8 + c0;
            *(float2*)(park + r0 * 260 + col)       = make_float2(acc2[t * 4 + 0], acc2[t * 4 + 1]);
            *(float2*)(park + (r0 + 8) * 260 + col) = make_float2(acc2[t * 4 + 2], acc2[t * 4 + 3]);
        }
    }
    __syncthreads();

    // ---- spline + logdet ----
    {
        const int m2 = tid >> 3;
        const int dg = tid & 7;
        float pr[31];
        #pragma unroll
        for (int j = 0; j < 31; j++)
            pr[j] = park[m2 * 260 + dg * 31 + j] + B2[dg * 31 + j];

        const int tdim = insert_bit(dg, p, 1 - cbit);
        const float xv = g_z[(row0 + m2) * DIMS + tdim];

        float ww[BINS], hh[BINS], dd[BINS + 1];
        float mx = pr[0];
        #pragma unroll
        for (int i = 1; i < BINS; i++) mx = fmaxf(mx, pr[i]);
        float ssum = 0.f;
        #pragma unroll
        for (int i = 0; i < BINS; i++) { ww[i] = expf(pr[i] - mx); ssum += ww[i]; }
        float sc = (1.0f - MIN_W * (float)BINS) / ssum;
        #pragma unroll
        for (int i = 0; i < BINS; i++) ww[i] = MIN_W + ww[i] * sc;

        mx = pr[BINS];
        #pragma unroll
        for (int i = 1; i < BINS; i++) mx = fmaxf(mx, pr[BINS + i]);
        ssum = 0.f;
        #pragma unroll
        for (int i = 0; i < BINS; i++) { hh[i] = expf(pr[BINS + i] - mx); ssum += hh[i]; }
        sc = (1.0f - MIN_H * (float)BINS) / ssum;
        #pragma unroll
        for (int i = 0; i < BINS; i++) hh[i] = MIN_H + hh[i] * sc;

        #pragma unroll
        for (int i = 0; i <= BINS; i++) {
            float u = pr[2 * BINS + i];
            dd[i] = MIN_D + (fmaxf(u, 0.f) + log1pf(expf(-fabsf(u))));
        }

        float cw[BINS + 1], ch[BINS + 1];
        cw[0] = 0.f; ch[0] = 0.f;
        #pragma unroll
        for (int i = 1; i <= BINS; i++) { cw[i] = cw[i-1] + ww[i-1]; ch[i] = ch[i-1] + hh[i-1]; }

        int cnt = 0;
        #pragma unroll
        for (int i = 0; i <= BINS; i++) cnt += (xv >= cw[i]) ? 1 : 0;
        int idx = cnt - 1;
        idx = idx < 0 ? 0 : (idx > BINS - 1 ? BINS - 1 : idx);

        float xk = 0.f, wk = 1.f, yk = 0.f, hk = 1.f, dk = 1.f, dk1 = 1.f;
        #pragma unroll
        for (int i = 0; i < BINS; i++)
            if (i == idx) { xk = cw[i]; wk = ww[i]; yk = ch[i]; hk = hh[i]; dk = dd[i]; dk1 = dd[i+1]; }

        float th  = fminf(fmaxf((xv - xk) / wk, 0.f), 1.f);
        float sr  = hk / wk;
        float t1  = th * (1.f - th);
        float den = sr + (dk1 + dk - 2.f * sr) * t1;
        float y   = yk + hk * (sr * th * th + dk * t1) / den;
        float omt = 1.f - th;
        float ld  = 2.f * logf(sr)
                  + logf(dk1 * th * th + 2.f * sr * t1 + dk * omt * omt)
                  - 2.f * logf(den);

        g_z[(row0 + m2) * DIMS + tdim] = y;

        #pragma unroll
        for (int off = 4; off > 0; off >>= 1)
            ld += __shfl_down_sync(0xffffffffu, ld, off);
        if (dg == 0) out[row0 + m2] += ld;
    }
}

extern "C" void kernel_launch(void* const* d_in, const int* in_sizes, int n_in,
                              void* d_out, int out_size) {
    const float* x  = (const float*)d_in[0];
    const float* c  = (const float*)d_in[1];
    const float* W0 = (const float*)d_in[2];
    const float* b0 = (const float*)d_in[3];
    const float* W1 = (const float*)d_in[4];
    const float* b1 = (const float*)d_in[5];
    const float* W2 = (const float*)d_in[6];
    const float* b2 = (const float*)d_in[7];
    float* out = (float*)d_out;

    cudaFuncSetAttribute(flow_block_kernel,
                         cudaFuncAttributeMaxDynamicSharedMemorySize, SMEM_TOTAL);

    init_kernel<<<(NS * DIMS + 255) / 256, 256>>>(x, out);
    prep_kernel<<<NBLOCKS * 100, 256>>>(W0, W1, W2);

    for (int b = 0; b < NBLOCKS; b++) {
        flow_block_kernel<<<NS / MTS, NTHREADS, SMEM_TOTAL>>>(
            b, c,
            b0 + (size_t)b * UNITS,
            b1 + (size_t)b * UNITS,
            b2 + (size_t)b * FEAT_OUT,
            out);
    }
}

// round 8
// speedup vs baseline: 23.3028x; 1.1648x over previous
#include <cuda_runtime.h>
#include <cuda_fp16.h>
#include <math.h>
#include <stdint.h>

#define NS       131072
#define DIMS     16
#define DIMSC    16
#define UNITS    512
#define BINS     10
#define DT       8
#define FEAT_IN  24
#define FEAT_OUT 248
#define NBLOCKS  8
#define MIN_W    0.001f
#define MIN_H    0.001f
#define MIN_D    0.001f

#define MTS      64
#define NTHREADS 512

// activation rows padded to 520 fp16 (1040 B, odd multiple of 16B -> conflict-free ldmatrix)
#define PADH     520
#define PADW     520
#define PADW2    264

// g_img per-flow-block layout (bytes) — UNCHANGED from round 7:
//  L0: 2 chunks x 33280   (chunk = 16 k-rows: hi plane 16640 + lo plane 16640)
//  L1: 32 chunks x 33280
//  L2: 16 chunks x 33792  (chunk = 32 k-rows: hi 16896 + lo 16896)
#define L0_OFF   0
#define L1_OFF   66560
#define L2_OFF   1131520
#define BLK_BYTES 1672192

// smem byte offsets
#define OFF_AH   0         // activation [64 x 520] fp16 = 66560 (also fp32 park 64x260)
#define OFF_W    66560     // 2 weight slots x 67584 = 135168
#define WSLOT    67584
#define OFF_IH   201728    // input tile hi [64 x 40] fp16 = 5120
#define OFF_IL   206848    // input tile lo
#define SMEM_TOTAL 211968

__device__ float g_z[NS * DIMS];
__device__ __align__(16) uint8_t g_img[(size_t)NBLOCKS * BLK_BYTES];

__device__ __forceinline__ uint32_t smem_u32(const void* p) {
    return (uint32_t)__cvta_generic_to_shared(p);
}
#define CP16(s, g)  asm volatile("cp.async.cg.shared.global [%0], [%1], 16;" :: "r"(s), "l"(g))
#define CPCOMMIT()  asm volatile("cp.async.commit_group;")
#define CPWAIT1()   asm volatile("cp.async.wait_group 1;" ::: "memory")
#define CPWAIT0()   asm volatile("cp.async.wait_group 0;" ::: "memory")

__device__ __forceinline__ void ldm4(uint32_t* r, uint32_t a) {
    asm volatile("ldmatrix.sync.aligned.m8n8.x4.shared.b16 {%0,%1,%2,%3}, [%4];"
        : "=r"(r[0]), "=r"(r[1]), "=r"(r[2]), "=r"(r[3]) : "r"(a));
}
__device__ __forceinline__ void ldm4t(uint32_t* r, uint32_t a) {
    asm volatile("ldmatrix.sync.aligned.m8n8.x4.trans.shared.b16 {%0,%1,%2,%3}, [%4];"
        : "=r"(r[0]), "=r"(r[1]), "=r"(r[2]), "=r"(r[3]) : "r"(a));
}
__device__ __forceinline__ void mma16816(float* d, const uint32_t* a, uint32_t b0, uint32_t b1) {
    asm volatile("mma.sync.aligned.m16n8k16.row.col.f32.f16.f16.f32 "
        "{%0,%1,%2,%3}, {%4,%5,%6,%7}, {%8,%9}, {%0,%1,%2,%3};"
        : "+f"(d[0]), "+f"(d[1]), "+f"(d[2]), "+f"(d[3])
        : "r"(a[0]), "r"(a[1]), "r"(a[2]), "r"(a[3]), "r"(b0), "r"(b1));
}
__device__ __forceinline__ int insert_bit(int f, int p, int bit) {
    int lo = f & ((1 << p) - 1);
    int hi = f >> p;
    return (hi << (p + 1)) | (bit << p) | lo;
}

// ---------------- init ----------------
__global__ void init_kernel(const float* __restrict__ x, float* __restrict__ out) {
    int i = blockIdx.x * blockDim.x + threadIdx.x;
    if (i < NS * DIMS) g_z[i] = x[i];
    if (i < NS) out[i] = 0.f;
}

// ---------------- weight image prep: fp16 hi/lo planes, padded rows ----------------
__global__ void prep_kernel(const float* __restrict__ W0,
                            const float* __restrict__ W1,
                            const float* __restrict__ W2) {
    int plane = blockIdx.x;
    int b = plane / 100, r = plane % 100;
    uint8_t* gb = g_img + (size_t)b * BLK_BYTES;
    int layer, chunk, half;
    if (r < 4)       { layer = 0; chunk = r >> 1;        half = r & 1; }
    else if (r < 68) { int q = r - 4;  layer = 1; chunk = q >> 1; half = q & 1; }
    else             { int q = r - 68; layer = 2; chunk = q >> 1; half = q & 1; }

    int rows  = (layer == 2) ? 32 : 16;
    int padc  = (layer == 2) ? PADW2 : PADW;
    int ncols = (layer == 2) ? FEAT_OUT : UNITS;
    uint8_t* dst;
    if (layer == 0)      dst = gb + L0_OFF + chunk * 33280 + half * 16640;
    else if (layer == 1) dst = gb + L1_OFF + chunk * 33280 + half * 16640;
    else                 dst = gb + L2_OFF + chunk * 33792 + half * 16896;
    __half* d16 = (__half*)dst;

    for (int i = threadIdx.x; i < rows * padc; i += blockDim.x) {
        int row = i / padc, col = i % padc;
        int k = chunk * rows + row;
        float w = 0.f;
        if (col < ncols) {
            if (layer == 0)      { if (k < FEAT_IN) w = W0[((size_t)b * FEAT_IN + k) * UNITS + col]; }
            else if (layer == 1) { w = W1[((size_t)b * UNITS + k) * UNITS + col]; }
            else                 { w = W2[((size_t)b * UNITS + k) * FEAT_OUT + col]; }
        }
        __half hi = __float2half(w);
        float v = half ? (w - __half2float(hi)) : w;
        d16[i] = __float2half(v);
    }
}

// ---------------- helpers ----------------
__device__ __forceinline__ void copy16(uint32_t sdst, const uint8_t* g, int n16, int tid) {
    for (int i = tid; i < n16; i += NTHREADS)
        CP16(sdst + i * 16, g + (size_t)i * 16);
}

// epilogue for L0/L1: bias+relu, store fp16 into activation tile (16 n8-tiles)
__device__ __forceinline__ void epi_h(float* acc /*64*/, const float* __restrict__ bias,
                                      uint8_t* sm, int mw, int nw, int lane) {
    int r0 = mw * 16 + (lane >> 2);
    int c0 = (lane & 3) * 2;
    uint8_t* AH = sm + OFF_AH;
    #pragma unroll
    for (int t = 0; t < 16; t++) {
        int col = nw * 128 + t * 8 + c0;
        float bx = bias[col], by = bias[col + 1];
        #pragma unroll
        for (int rr = 0; rr < 2; rr++) {
            float vx = fmaxf(acc[t * 4 + rr * 2 + 0] + bx, 0.f);
            float vy = fmaxf(acc[t * 4 + rr * 2 + 1] + by, 0.f);
            int row = r0 + rr * 8;
            uint32_t off = (uint32_t)(row * PADH + col) * 2;
            *(__half2*)(AH + off) = __halves2half2(__float2half(vx), __float2half(vy));
        }
    }
}

// ---------------- main fused flow-block kernel ----------------
__global__ void __launch_bounds__(NTHREADS, 1)
flow_block_kernel(int blk,
                  const float* __restrict__ cc,
                  const float* __restrict__ B0, const float* __restrict__ B1,
                  const float* __restrict__ B2,
                  float* __restrict__ out)
{
    extern __shared__ __align__(128) uint8_t sm[];
    const uint32_t s0 = smem_u32(sm);
    const int tid  = threadIdx.x;
    const int wid  = tid >> 5;
    const int lane = tid & 31;
    const int mw   = wid & 3;     // sample group (16 rows)
    const int nw   = wid >> 2;    // column group (128 cols for L0/L1, 64 for L2)
    const int row0 = blockIdx.x * MTS;
    const int p    = blk >> 1;
    const int cbit = 1 - (blk & 1);
    const uint8_t* gb = g_img + (size_t)blk * BLK_BYTES;

    const int l15  = lane & 15;
    const int lhi  = lane >> 4;
    const int arow = mw * 16 + l15;
    const uint32_t aoffA = (uint32_t)(arow * (PADH * 2)) + lhi * 16;
    const uint32_t aoffI = (uint32_t)(arow * 80)         + lhi * 16;
    const int krow = (lane & 7) + ((lane >> 3) & 1) * 8;
    const uint32_t woff1 = (uint32_t)(krow * (PADW * 2))  + (uint32_t)lhi * 16;
    const uint32_t woff2 = (uint32_t)(krow * (PADW2 * 2)) + (uint32_t)lhi * 16;

    // ---- stage L0 weights (both image chunks = 66560 B) ----
    copy16(s0 + OFF_W, gb + L0_OFF, 4160, tid);
    CPCOMMIT();

    // ---- build input tile [64 x 32] fp16 hi/lo, zero-padded ----
    for (int i = tid; i < 1280; i += NTHREADS) {
        ((uint32_t*)(sm + OFF_IH))[i] = 0u;
        ((uint32_t*)(sm + OFF_IL))[i] = 0u;
    }
    __syncthreads();
    for (int i = tid; i < MTS * FEAT_IN; i += NTHREADS) {
        int m = i / FEAT_IN, f = i % FEAT_IN;
        float v = (f < DT) ? g_z[(row0 + m) * DIMS + insert_bit(f, p, cbit)]
                           : cc[(row0 + m) * DIMSC + (f - DT)];
        __half hi = __float2half(v);
        ((__half*)(sm + OFF_IH))[m * 40 + f] = hi;
        ((__half*)(sm + OFF_IL))[m * 40 + f] = __float2half(v - __half2float(hi));
    }
    CPWAIT0();
    __syncthreads();

    float acc[64];
    #pragma unroll
    for (int i = 0; i < 64; i++) acc[i] = 0.f;

    // ---- L0: 2 ksteps, 128 cols/warp, 3-pass (input hi/lo + weight hi/lo) ----
    #pragma unroll
    for (int ks = 0; ks < 2; ks++) {
        uint32_t ah[4], al[4];
        ldm4(ah, s0 + OFF_IH + aoffI + ks * 32);
        ldm4(al, s0 + OFF_IL + aoffI + ks * 32);
        uint32_t wb = s0 + OFF_W + ks * 33280;
        #pragma unroll
        for (int np = 0; np < 8; np++) {
            uint32_t bh[4], bl[4];
            uint32_t ba = wb + woff1 + (uint32_t)(nw * 128 + np * 16) * 2;
            ldm4t(bh, ba);
            ldm4t(bl, ba + 16640);
            float* d0 = acc + (2 * np) * 4;
            float* d1 = acc + (2 * np + 1) * 4;
            mma16816(d0, ah, bh[0], bh[1]);
            mma16816(d1, ah, bh[2], bh[3]);
            mma16816(d0, ah, bl[0], bl[1]);
            mma16816(d1, ah, bl[2], bl[3]);
            mma16816(d0, al, bh[0], bh[1]);
            mma16816(d1, al, bh[2], bh[3]);
        }
    }
    __syncthreads();

    // ---- L1 prologue: k32 chunk 0, then epilogue0 overlapped ----
    copy16(s0 + OFF_W, gb + L1_OFF, 4160, tid);
    CPCOMMIT();
    epi_h(acc, B0, sm, mw, nw, lane);
    #pragma unroll
    for (int i = 0; i < 64; i++) acc[i] = 0.f;

    // ---- L1: 16 k32-chunks streamed, 128 cols/warp ----
    for (int c = 0; c < 16; c++) {
        if (c + 1 < 16) {
            copy16(s0 + OFF_W + ((c + 1) & 1) * WSLOT, gb + L1_OFF + (size_t)(c + 1) * 66560, 4160, tid);
            CPCOMMIT();
            CPWAIT1();
        } else {
            CPWAIT0();
        }
        __syncthreads();
        uint32_t buf = s0 + OFF_W + (c & 1) * WSLOT;
        #pragma unroll
        for (int ks2 = 0; ks2 < 2; ks2++) {
            uint32_t ah[4];
            ldm4(ah, s0 + OFF_AH + aoffA + (uint32_t)(c * 64 + ks2 * 32));
            uint32_t wb = buf + ks2 * 33280;
            #pragma unroll
            for (int np = 0; np < 8; np++) {
                uint32_t bh[4], bl[4];
                uint32_t ba = wb + woff1 + (uint32_t)(nw * 128 + np * 16) * 2;
                ldm4t(bh, ba);
                ldm4t(bl, ba + 16640);
                float* d0 = acc + (2 * np) * 4;
                float* d1 = acc + (2 * np + 1) * 4;
                mma16816(d0, ah, bh[0], bh[1]);
                mma16816(d1, ah, bh[2], bh[3]);
                mma16816(d0, ah, bl[0], bl[1]);
                mma16816(d1, ah, bl[2], bl[3]);
            }
        }
        __syncthreads();
    }

    // ---- L2 prologue (k64 chunk 0) + epilogue1 ----
    copy16(s0 + OFF_W, gb + L2_OFF, 4224, tid);
    CPCOMMIT();
    epi_h(acc, B1, sm, mw, nw, lane);

    float acc2[32];
    #pragma unroll
    for (int i = 0; i < 32; i++) acc2[i] = 0.f;

    // ---- L2: 8 k64-chunks streamed, 64 cols/warp ----
    for (int c = 0; c < 8; c++) {
        if (c + 1 < 8) {
            copy16(s0 + OFF_W + ((c + 1) & 1) * WSLOT, gb + L2_OFF + (size_t)(c + 1) * 67584, 4224, tid);
            CPCOMMIT();
            CPWAIT1();
        } else {
            CPWAIT0();
        }
        __syncthreads();
        uint32_t buf = s0 + OFF_W + (c & 1) * WSLOT;
        #pragma unroll
        for (int sub = 0; sub < 2; sub++) {
            uint32_t wbs = buf + sub * 33792;
            #pragma unroll
            for (int ks = 0; ks < 2; ks++) {
                uint32_t ah[4];
                ldm4(ah, s0 + OFF_AH + aoffA + (uint32_t)(c * 128 + sub * 64 + ks * 32));
                #pragma unroll
                for (int np = 0; np < 4; np++) {
                    uint32_t bh[4], bl[4];
                    uint32_t ba = wbs + (uint32_t)(ks * 16 * PADW2 * 2) + woff2
                                + (uint32_t)(nw * 64 + np * 16) * 2;
                    ldm4t(bh, ba);
                    ldm4t(bl, ba + 16896);
                    float* d0 = acc2 + (2 * np) * 4;
                    float* d1 = acc2 + (2 * np + 1) * 4;
                    mma16816(d0, ah, bh[0], bh[1]);
                    mma16816(d1, ah, bh[2], bh[3]);
                    mma16816(d0, ah, bl[0], bl[1]);
                    mma16816(d1, ah, bl[2], bl[3]);
                }
            }
        }
        __syncthreads();
    }

    // ---- park params fp32 into AH region (h dead) ----
    float* park = (float*)(sm + OFF_AH);
    {
        int r0 = mw * 16 + (lane >> 2);
        int c0 = (lane & 3) * 2;
        #pragma unroll
        for (int t = 0; t < 8; t++) {
            int col = nw * 64 + t * 8 + c0;
            *(float2*)(park + r0 * 260 + col)       = make_float2(acc2[t * 4 + 0], acc2[t * 4 + 1]);
            *(float2*)(park + (r0 + 8) * 260 + col) = make_float2(acc2[t * 4 + 2], acc2[t * 4 + 3]);
        }
    }
    __syncthreads();

    // ---- spline + logdet ----
    {
        const int m2 = tid >> 3;
        const int dg = tid & 7;
        float pr[31];
        #pragma unroll
        for (int j = 0; j < 31; j++)
            pr[j] = park[m2 * 260 + dg * 31 + j] + B2[dg * 31 + j];

        const int tdim = insert_bit(dg, p, 1 - cbit);
        const float xv = g_z[(row0 + m2) * DIMS + tdim];

        float ww[BINS], hh[BINS], dd[BINS + 1];
        float mx = pr[0];
        #pragma unroll
        for (int i = 1; i < BINS; i++) mx = fmaxf(mx, pr[i]);
        float ssum = 0.f;
        #pragma unroll
        for (int i = 0; i < BINS; i++) { ww[i] = expf(pr[i] - mx); ssum += ww[i]; }
        float sc = (1.0f - MIN_W * (float)BINS) / ssum;
        #pragma unroll
        for (int i = 0; i < BINS; i++) ww[i] = MIN_W + ww[i] * sc;

        mx = pr[BINS];
        #pragma unroll
        for (int i = 1; i < BINS; i++) mx = fmaxf(mx, pr[BINS + i]);
        ssum = 0.f;
        #pragma unroll
        for (int i = 0; i < BINS; i++) { hh[i] = expf(pr[BINS + i] - mx); ssum += hh[i]; }
        sc = (1.0f - MIN_H * (float)BINS) / ssum;
        #pragma unroll
        for (int i = 0; i < BINS; i++) hh[i] = MIN_H + hh[i] * sc;

        #pragma unroll
        for (int i = 0; i <= BINS; i++) {
            float u = pr[2 * BINS + i];
            dd[i] = MIN_D + (fmaxf(u, 0.f) + log1pf(expf(-fabsf(u))));
        }

        float cw[BINS + 1], ch[BINS + 1];
        cw[0] = 0.f; ch[0] = 0.f;
        #pragma unroll
        for (int i = 1; i <= BINS; i++) { cw[i] = cw[i-1] + ww[i-1]; ch[i] = ch[i-1] + hh[i-1]; }

        int cnt = 0;
        #pragma unroll
        for (int i = 0; i <= BINS; i++) cnt += (xv >= cw[i]) ? 1 : 0;
        int idx = cnt - 1;
        idx = idx < 0 ? 0 : (idx > BINS - 1 ? BINS - 1 : idx);

        float xk = 0.f, wk = 1.f, yk = 0.f, hk = 1.f, dk = 1.f, dk1 = 1.f;
        #pragma unroll
        for (int i = 0; i < BINS; i++)
            if (i == idx) { xk = cw[i]; wk = ww[i]; yk = ch[i]; hk = hh[i]; dk = dd[i]; dk1 = dd[i+1]; }

        float th  = fminf(fmaxf((xv - xk) / wk, 0.f), 1.f);
        float sr  = hk / wk;
        float t1  = th * (1.f - th);
        float den = sr + (dk1 + dk - 2.f * sr) * t1;
        float y   = yk + hk * (sr * th * th + dk * t1) / den;
        float omt = 1.f - th;
        float ld  = 2.f * logf(sr)
                  + logf(dk1 * th * th + 2.f * sr * t1 + dk * omt * omt)
                  - 2.f * logf(den);

        g_z[(row0 + m2) * DIMS + tdim] = y;

        #pragma unroll
        for (int off = 4; off > 0; off >>= 1)
            ld += __shfl_down_sync(0xffffffffu, ld, off);
        if (dg == 0) out[row0 + m2] += ld;
    }
}

extern "C" void kernel_launch(void* const* d_in, const int* in_sizes, int n_in,
                              void* d_out, int out_size) {
    const float* x  = (const float*)d_in[0];
    const float* c  = (const float*)d_in[1];
    const float* W0 = (const float*)d_in[2];
    const float* b0 = (const float*)d_in[3];
    const float* W1 = (const float*)d_in[4];
    const float* b1 = (const float*)d_in[5];
    const float* W2 = (const float*)d_in[6];
    const float* b2 = (const float*)d_in[7];
    float* out = (float*)d_out;

    cudaFuncSetAttribute(flow_block_kernel,
                         cudaFuncAttributeMaxDynamicSharedMemorySize, SMEM_TOTAL);

    init_kernel<<<(NS * DIMS + 255) / 256, 256>>>(x, out);
    prep_kernel<<<NBLOCKS * 100, 256>>>(W0, W1, W2);

    for (int b = 0; b < NBLOCKS; b++) {
        flow_block_kernel<<<NS / MTS, NTHREADS, SMEM_TOTAL>>>(
            b, c,
            b0 + (size_t)b * UNITS,
            b1 + (size_t)b * UNITS,
            b2 + (size_t)b * FEAT_OUT,
            out);
    }
}

// round 9
// speedup vs baseline: 25.7824x; 1.1064x over previous
#include <cuda_runtime.h>
#include <cuda_fp16.h>
#include <math.h>
#include <stdint.h>

#define NS       131072
#define DIMS     16
#define DIMSC    16
#define UNITS    512
#define BINS     10
#define DT       8
#define FEAT_IN  24
#define FEAT_OUT 248
#define NBLOCKS  8
#define MIN_W    0.001f
#define MIN_H    0.001f
#define MIN_D    0.001f

#define MTS      64
#define NTHREADS 512

#define PADH     520
#define PADW     520
#define PADW2    264

// g_img per-flow-block layout (bytes) — unchanged:
//  L0: 2 chunks x 33280   (chunk = 16 k-rows: hi 16640 + lo 16640)
//  L1: 32 chunks x 33280
//  L2: 16 chunks x 33792  (chunk = 32 k-rows: hi 16896 + lo 16896)
#define L0_OFF   0
#define L1_OFF   66560
#define L2_OFF   1131520
#define BLK_BYTES 1672192

// smem byte offsets
#define OFF_AH   0         // activation [64 x 520] fp16 = 66560 (also fp32 park 64x260)
#define OFF_W    66560     // 2 weight slots x 67584
#define WSLOT    67584
#define OFF_IH   201728    // input tile hi [64 x 40] fp16
#define OFF_IL   206848    // input tile lo
#define SMEM_TOTAL 211968

__device__ float g_z[NS * DIMS];
__device__ __align__(16) uint8_t g_img[(size_t)NBLOCKS * BLK_BYTES];

__device__ __forceinline__ uint32_t smem_u32(const void* p) {
    return (uint32_t)__cvta_generic_to_shared(p);
}
#define CP16(s, g)  asm volatile("cp.async.cg.shared.global [%0], [%1], 16;" :: "r"(s), "l"(g))
#define CPCOMMIT()  asm volatile("cp.async.commit_group;")
#define CPWAIT1()   asm volatile("cp.async.wait_group 1;" ::: "memory")
#define CPWAIT0()   asm volatile("cp.async.wait_group 0;" ::: "memory")

__device__ __forceinline__ void ldm4(uint32_t* r, uint32_t a) {
    asm volatile("ldmatrix.sync.aligned.m8n8.x4.shared.b16 {%0,%1,%2,%3}, [%4];"
        : "=r"(r[0]), "=r"(r[1]), "=r"(r[2]), "=r"(r[3]) : "r"(a));
}
__device__ __forceinline__ void ldm4t(uint32_t* r, uint32_t a) {
    asm volatile("ldmatrix.sync.aligned.m8n8.x4.trans.shared.b16 {%0,%1,%2,%3}, [%4];"
        : "=r"(r[0]), "=r"(r[1]), "=r"(r[2]), "=r"(r[3]) : "r"(a));
}
__device__ __forceinline__ void mma16816(float* d, const uint32_t* a, uint32_t b0, uint32_t b1) {
    asm volatile("mma.sync.aligned.m16n8k16.row.col.f32.f16.f16.f32 "
        "{%0,%1,%2,%3}, {%4,%5,%6,%7}, {%8,%9}, {%0,%1,%2,%3};"
        : "+f"(d[0]), "+f"(d[1]), "+f"(d[2]), "+f"(d[3])
        : "r"(a[0]), "r"(a[1]), "r"(a[2]), "r"(a[3]), "r"(b0), "r"(b1));
}
__device__ __forceinline__ int insert_bit(int f, int p, int bit) {
    int lo = f & ((1 << p) - 1);
    int hi = f >> p;
    return (hi << (p + 1)) | (bit << p) | lo;
}

// ---------------- init ----------------
__global__ void init_kernel(const float* __restrict__ x, float* __restrict__ out) {
    int i = blockIdx.x * blockDim.x + threadIdx.x;
    if (i < NS * DIMS) g_z[i] = x[i];
    if (i < NS) out[i] = 0.f;
}

// ---------------- weight image prep (unchanged) ----------------
__global__ void prep_kernel(const float* __restrict__ W0,
                            const float* __restrict__ W1,
                            const float* __restrict__ W2) {
    int plane = blockIdx.x;
    int b = plane / 100, r = plane % 100;
    uint8_t* gb = g_img + (size_t)b * BLK_BYTES;
    int layer, chunk, half;
    if (r < 4)       { layer = 0; chunk = r >> 1;        half = r & 1; }
    else if (r < 68) { int q = r - 4;  layer = 1; chunk = q >> 1; half = q & 1; }
    else             { int q = r - 68; layer = 2; chunk = q >> 1; half = q & 1; }

    int rows  = (layer == 2) ? 32 : 16;
    int padc  = (layer == 2) ? PADW2 : PADW;
    int ncols = (layer == 2) ? FEAT_OUT : UNITS;
    uint8_t* dst;
    if (layer == 0)      dst = gb + L0_OFF + chunk * 33280 + half * 16640;
    else if (layer == 1) dst = gb + L1_OFF + chunk * 33280 + half * 16640;
    else                 dst = gb + L2_OFF + chunk * 33792 + half * 16896;
    __half* d16 = (__half*)dst;

    for (int i = threadIdx.x; i < rows * padc; i += blockDim.x) {
        int row = i / padc, col = i % padc;
        int k = chunk * rows + row;
        float w = 0.f;
        if (col < ncols) {
            if (layer == 0)      { if (k < FEAT_IN) w = W0[((size_t)b * FEAT_IN + k) * UNITS + col]; }
            else if (layer == 1) { w = W1[((size_t)b * UNITS + k) * UNITS + col]; }
            else                 { w = W2[((size_t)b * UNITS + k) * FEAT_OUT + col]; }
        }
        __half hi = __float2half(w);
        float v = half ? (w - __half2float(hi)) : w;
        d16[i] = __float2half(v);
    }
}

// ---------------- helpers ----------------
__device__ __forceinline__ void copy16(uint32_t sdst, const uint8_t* g, int n16, int tid) {
    for (int i = tid; i < n16; i += NTHREADS)
        CP16(sdst + i * 16, g + (size_t)i * 16);
}

// epilogue L0/L1: bias+relu -> fp16 activation tile.  warp = m32 x n64
// acc layout: acc[np*16 + mh*8 + j*4 + rr*2 + e], np 0..3 (n16), mh 0..1 (m16), j 0..1 (n8)
__device__ __forceinline__ void epi_h(float* acc, const float* __restrict__ bias,
                                      uint8_t* sm, int mw, int nw, int lane) {
    int rb = mw * 32 + (lane >> 2);
    int c0 = (lane & 3) * 2;
    uint8_t* AH = sm + OFF_AH;
    #pragma unroll
    for (int np = 0; np < 4; np++) {
        #pragma unroll
        for (int j = 0; j < 2; j++) {
            int col = nw * 64 + np * 16 + j * 8 + c0;
            float bx = bias[col], by = bias[col + 1];
            #pragma unroll
            for (int mh = 0; mh < 2; mh++) {
                float* a = acc + np * 16 + mh * 8 + j * 4;
                #pragma unroll
                for (int rr = 0; rr < 2; rr++) {
                    float vx = fmaxf(a[rr * 2 + 0] + bx, 0.f);
                    float vy = fmaxf(a[rr * 2 + 1] + by, 0.f);
                    int row = rb + mh * 16 + rr * 8;
                    uint32_t off = (uint32_t)(row * PADH + col) * 2;
                    *(__half2*)(AH + off) = __halves2half2(__float2half(vx), __float2half(vy));
                }
            }
        }
    }
}

// ---------------- main fused flow-block kernel ----------------
__global__ void __launch_bounds__(NTHREADS, 1)
flow_block_kernel(int blk,
                  const float* __restrict__ cc,
                  const float* __restrict__ B0, const float* __restrict__ B1,
                  const float* __restrict__ B2,
                  float* __restrict__ out)
{
    extern __shared__ __align__(128) uint8_t sm[];
    const uint32_t s0 = smem_u32(sm);
    const int tid  = threadIdx.x;
    const int wid  = tid >> 5;
    const int lane = tid & 31;
    const int mw   = wid & 1;     // 2 sample groups of 32 rows
    const int nw   = wid >> 1;    // 8 column groups (64 cols L0/L1, 32 cols L2)
    const int row0 = blockIdx.x * MTS;
    const int p    = blk >> 1;
    const int cbit = 1 - (blk & 1);
    const uint8_t* gb = g_img + (size_t)blk * BLK_BYTES;

    const int l15  = lane & 15;
    const int lhi  = lane >> 4;
    const int ar0  = mw * 32 + l15;          // m16 half 0
    const uint32_t aoff0 = (uint32_t)(ar0 * (PADH * 2)) + lhi * 16;
    const uint32_t aoff1 = aoff0 + 16 * (PADH * 2);
    const uint32_t ioff0 = (uint32_t)(ar0 * 80) + lhi * 16;
    const uint32_t ioff1 = ioff0 + 16 * 80;
    const int krow = (lane & 7) + ((lane >> 3) & 1) * 8;
    const uint32_t woff1 = (uint32_t)(krow * (PADW * 2))  + (uint32_t)lhi * 16;
    const uint32_t woff2 = (uint32_t)(krow * (PADW2 * 2)) + (uint32_t)lhi * 16;

    // ---- stage L0 weights (66560 B) ----
    copy16(s0 + OFF_W, gb + L0_OFF, 4160, tid);
    CPCOMMIT();

    // ---- build input tile [64 x 32] fp16 hi/lo, zero-padded ----
    for (int i = tid; i < 1280; i += NTHREADS) {
        ((uint32_t*)(sm + OFF_IH))[i] = 0u;
        ((uint32_t*)(sm + OFF_IL))[i] = 0u;
    }
    __syncthreads();
    for (int i = tid; i < MTS * FEAT_IN; i += NTHREADS) {
        int m = i / FEAT_IN, f = i % FEAT_IN;
        float v = (f < DT) ? g_z[(row0 + m) * DIMS + insert_bit(f, p, cbit)]
                           : cc[(row0 + m) * DIMSC + (f - DT)];
        __half hi = __float2half(v);
        ((__half*)(sm + OFF_IH))[m * 40 + f] = hi;
        ((__half*)(sm + OFF_IL))[m * 40 + f] = __float2half(v - __half2float(hi));
    }
    CPWAIT0();
    __syncthreads();

    float acc[64];
    #pragma unroll
    for (int i = 0; i < 64; i++) acc[i] = 0.f;

    // ---- L0: 2 k16-steps, 3-pass (weight hi/lo + input lo) ----
    #pragma unroll
    for (int ks = 0; ks < 2; ks++) {
        uint32_t ah0[4], ah1[4], al0[4], al1[4];
        ldm4(ah0, s0 + OFF_IH + ioff0 + ks * 32);
        ldm4(ah1, s0 + OFF_IH + ioff1 + ks * 32);
        ldm4(al0, s0 + OFF_IL + ioff0 + ks * 32);
        ldm4(al1, s0 + OFF_IL + ioff1 + ks * 32);
        uint32_t wb = s0 + OFF_W + ks * 33280;
        #pragma unroll
        for (int np = 0; np < 4; np++) {
            uint32_t bh[4], bl[4];
            uint32_t ba = wb + woff1 + (uint32_t)(nw * 64 + np * 16) * 2;
            ldm4t(bh, ba);
            ldm4t(bl, ba + 16640);
            float* d00 = acc + np * 16;
            float* d01 = acc + np * 16 + 4;
            float* d10 = acc + np * 16 + 8;
            float* d11 = acc + np * 16 + 12;
            mma16816(d00, ah0, bh[0], bh[1]);
            mma16816(d10, ah1, bh[0], bh[1]);
            mma16816(d01, ah0, bh[2], bh[3]);
            mma16816(d11, ah1, bh[2], bh[3]);
            mma16816(d00, ah0, bl[0], bl[1]);
            mma16816(d10, ah1, bl[0], bl[1]);
            mma16816(d01, ah0, bl[2], bl[3]);
            mma16816(d11, ah1, bl[2], bl[3]);
            mma16816(d00, al0, bh[0], bh[1]);
            mma16816(d10, al1, bh[0], bh[1]);
            mma16816(d01, al0, bh[2], bh[3]);
            mma16816(d11, al1, bh[2], bh[3]);
        }
    }
    __syncthreads();

    // ---- L1 prologue: k32 chunk 0, epilogue0 overlapped ----
    copy16(s0 + OFF_W, gb + L1_OFF, 4160, tid);
    CPCOMMIT();
    epi_h(acc, B0, sm, mw, nw, lane);
    #pragma unroll
    for (int i = 0; i < 64; i++) acc[i] = 0.f;

    // ---- L1: 16 k32-chunks streamed ----
    for (int c = 0; c < 16; c++) {
        if (c + 1 < 16) {
            copy16(s0 + OFF_W + ((c + 1) & 1) * WSLOT, gb + L1_OFF + (size_t)(c + 1) * 66560, 4160, tid);
            CPCOMMIT();
            CPWAIT1();
        } else {
            CPWAIT0();
        }
        __syncthreads();
        uint32_t buf = s0 + OFF_W + (c & 1) * WSLOT;
        #pragma unroll
        for (int ks2 = 0; ks2 < 2; ks2++) {
            uint32_t ah0[4], ah1[4];
            uint32_t ao = (uint32_t)(c * 64 + ks2 * 32);
            ldm4(ah0, s0 + OFF_AH + aoff0 + ao);
            ldm4(ah1, s0 + OFF_AH + aoff1 + ao);
            uint32_t wb = buf + ks2 * 33280;
            #pragma unroll
            for (int np = 0; np < 4; np++) {
                uint32_t bh[4], bl[4];
                uint32_t ba = wb + woff1 + (uint32_t)(nw * 64 + np * 16) * 2;
                ldm4t(bh, ba);
                ldm4t(bl, ba + 16640);
                float* d00 = acc + np * 16;
                float* d01 = acc + np * 16 + 4;
                float* d10 = acc + np * 16 + 8;
                float* d11 = acc + np * 16 + 12;
                mma16816(d00, ah0, bh[0], bh[1]);
                mma16816(d10, ah1, bh[0], bh[1]);
                mma16816(d01, ah0, bh[2], bh[3]);
                mma16816(d11, ah1, bh[2], bh[3]);
                mma16816(d00, ah0, bl[0], bl[1]);
                mma16816(d10, ah1, bl[0], bl[1]);
                mma16816(d01, ah0, bl[2], bl[3]);
                mma16816(d11, ah1, bl[2], bl[3]);
            }
        }
        __syncthreads();
    }

    // ---- L2 prologue (k64 chunk 0) + epilogue1 ----
    copy16(s0 + OFF_W, gb + L2_OFF, 4224, tid);
    CPCOMMIT();
    epi_h(acc, B1, sm, mw, nw, lane);

    float acc2[32];
    #pragma unroll
    for (int i = 0; i < 32; i++) acc2[i] = 0.f;

    // ---- L2: 8 k64-chunks streamed, warp = m32 x n32 ----
    for (int c = 0; c < 8; c++) {
        if (c + 1 < 8) {
            copy16(s0 + OFF_W + ((c + 1) & 1) * WSLOT, gb + L2_OFF + (size_t)(c + 1) * 67584, 4224, tid);
            CPCOMMIT();
            CPWAIT1();
        } else {
            CPWAIT0();
        }
        __syncthreads();
        uint32_t buf = s0 + OFF_W + (c & 1) * WSLOT;
        #pragma unroll
        for (int sub = 0; sub < 2; sub++) {
            uint32_t wbs = buf + sub * 33792;
            #pragma unroll
            for (int ks = 0; ks < 2; ks++) {
                uint32_t ah0[4], ah1[4];
                uint32_t ao = (uint32_t)(c * 128 + sub * 64 + ks * 32);
                ldm4(ah0, s0 + OFF_AH + aoff0 + ao);
                ldm4(ah1, s0 + OFF_AH + aoff1 + ao);
                #pragma unroll
                for (int np = 0; np < 2; np++) {
                    uint32_t bh[4], bl[4];
                    uint32_t ba = wbs + (uint32_t)(ks * 16 * PADW2 * 2) + woff2
                                + (uint32_t)(nw * 32 + np * 16) * 2;
                    ldm4t(bh, ba);
                    ldm4t(bl, ba + 16896);
                    float* d00 = acc2 + np * 16;
                    float* d01 = acc2 + np * 16 + 4;
                    float* d10 = acc2 + np * 16 + 8;
                    float* d11 = acc2 + np * 16 + 12;
                    mma16816(d00, ah0, bh[0], bh[1]);
                    mma16816(d10, ah1, bh[0], bh[1]);
                    mma16816(d01, ah0, bh[2], bh[3]);
                    mma16816(d11, ah1, bh[2], bh[3]);
                    mma16816(d00, ah0, bl[0], bl[1]);
                    mma16816(d10, ah1, bl[0], bl[1]);
                    mma16816(d01, ah0, bl[2], bl[3]);
                    mma16816(d11, ah1, bl[2], bl[3]);
                }
            }
        }
        __syncthreads();
    }

    // ---- park params fp32 into AH region (h dead) ----
    float* park = (float*)(sm + OFF_AH);
    {
        int rb = mw * 32 + (lane >> 2);
        int c0 = (lane & 3) * 2;
        #pragma unroll
        for (int np = 0; np < 2; np++) {
            #pragma unroll
            for (int j = 0; j < 2; j++) {
                int col = nw * 32 + np * 16 + j * 8 + c0;
                #pragma unroll
                for (int mh = 0; mh < 2; mh++) {
                    float* a = acc2 + np * 16 + mh * 8 + j * 4;
                    #pragma unroll
                    for (int rr = 0; rr < 2; rr++) {
                        int row = rb + mh * 16 + rr * 8;
                        *(float2*)(park + row * 260 + col) = make_float2(a[rr * 2 + 0], a[rr * 2 + 1]);
                    }
                }
            }
        }
    }
    __syncthreads();

    // ---- spline + logdet ----
    {
        const int m2 = tid >> 3;
        const int dg = tid & 7;
        float pr[31];
        #pragma unroll
        for (int j = 0; j < 31; j++)
            pr[j] = park[m2 * 260 + dg * 31 + j] + B2[dg * 31 + j];

        const int tdim = insert_bit(dg, p, 1 - cbit);
        const float xv = g_z[(row0 + m2) * DIMS + tdim];

        float ww[BINS], hh[BINS], dd[BINS + 1];
        float mx = pr[0];
        #pragma unroll
        for (int i = 1; i < BINS; i++) mx = fmaxf(mx, pr[i]);
        float ssum = 0.f;
        #pragma unroll
        for (int i = 0; i < BINS; i++) { ww[i] = expf(pr[i] - mx); ssum += ww[i]; }
        float sc = (1.0f - MIN_W * (float)BINS) / ssum;
        #pragma unroll
        for (int i = 0; i < BINS; i++) ww[i] = MIN_W + ww[i] * sc;

        mx = pr[BINS];
        #pragma unroll
        for (int i = 1; i < BINS; i++) mx = fmaxf(mx, pr[BINS + i]);
        ssum = 0.f;
        #pragma unroll
        for (int i = 0; i < BINS; i++) { hh[i] = expf(pr[BINS + i] - mx); ssum += hh[i]; }
        sc = (1.0f - MIN_H * (float)BINS) / ssum;
        #pragma unroll
        for (int i = 0; i < BINS; i++) hh[i] = MIN_H + hh[i] * sc;

        #pragma unroll
        for (int i = 0; i <= BINS; i++) {
            float u = pr[2 * BINS + i];
            dd[i] = MIN_D + (fmaxf(u, 0.f) + log1pf(expf(-fabsf(u))));
        }

        float cw[BINS + 1], ch[BINS + 1];
        cw[0] = 0.f; ch[0] = 0.f;
        #pragma unroll
        for (int i = 1; i <= BINS; i++) { cw[i] = cw[i-1] + ww[i-1]; ch[i] = ch[i-1] + hh[i-1]; }

        int cnt = 0;
        #pragma unroll
        for (int i = 0; i <= BINS; i++) cnt += (xv >= cw[i]) ? 1 : 0;
        int idx = cnt - 1;
        idx = idx < 0 ? 0 : (idx > BINS - 1 ? BINS - 1 : idx);

        float xk = 0.f, wk = 1.f, yk = 0.f, hk = 1.f, dk = 1.f, dk1 = 1.f;
        #pragma unroll
        for (int i = 0; i < BINS; i++)
            if (i == idx) { xk = cw[i]; wk = ww[i]; yk = ch[i]; hk = hh[i]; dk = dd[i]; dk1 = dd[i+1]; }

        float th  = fminf(fmaxf((xv - xk) / wk, 0.f), 1.f);
        float sr  = hk / wk;
        float t1  = th * (1.f - th);
        float den = sr + (dk1 + dk - 2.f * sr) * t1;
        float y   = yk + hk * (sr * th * th + dk * t1) / den;
        float omt = 1.f - th;
        float ld  = 2.f * logf(sr)
                  + logf(dk1 * th * th + 2.f * sr * t1 + dk * omt * omt)
                  - 2.f * logf(den);

        g_z[(row0 + m2) * DIMS + tdim] = y;

        #pragma unroll
        for (int off = 4; off > 0; off >>= 1)
            ld += __shfl_down_sync(0xffffffffu, ld, off);
        if (dg == 0) out[row0 + m2] += ld;
    }
}

extern "C" void kernel_launch(void* const* d_in, const int* in_sizes, int n_in,
                              void* d_out, int out_size) {
    const float* x  = (const float*)d_in[0];
    const float* c  = (const float*)d_in[1];
    const float* W0 = (const float*)d_in[2];
    const float* b0 = (const float*)d_in[3];
    const float* W1 = (const float*)d_in[4];
    const float* b1 = (const float*)d_in[5];
    const float* W2 = (const float*)d_in[6];
    const float* b2 = (const float*)d_in[7];
    float* out = (float*)d_out;

    cudaFuncSetAttribute(flow_block_kernel,
                         cudaFuncAttributeMaxDynamicSharedMemorySize, SMEM_TOTAL);

    init_kernel<<<(NS * DIMS + 255) / 256, 256>>>(x, out);
    prep_kernel<<<NBLOCKS * 100, 256>>>(W0, W1, W2);

    for (int b = 0; b < NBLOCKS; b++) {
        flow_block_kernel<<<NS / MTS, NTHREADS, SMEM_TOTAL>>>(
            b, c,
            b0 + (size_t)b * UNITS,
            b1 + (size_t)b * UNITS,
            b2 + (size_t)b * FEAT_OUT,
            out);
    }
}

// round 10
// speedup vs baseline: 27.0731x; 1.0501x over previous
#include <cuda_runtime.h>
#include <cuda_fp16.h>
#include <math.h>
#include <stdint.h>

#define NS       131072
#define DIMS     16
#define DIMSC    16
#define UNITS    512
#define BINS     10
#define DT       8
#define FEAT_IN  24
#define FEAT_OUT 248
#define NBLOCKS  8
#define MIN_W    0.001f
#define MIN_H    0.001f
#define MIN_D    0.001f

#define MTS      64
#define NTHREADS 512

#define PADH     520
#define PADW     520
#define PADW2    264

// g_img per-flow-block layout (bytes) — unchanged:
//  L0: 2 chunks x 33280   (chunk = 16 k-rows: hi 16640 + lo 16640)
//  L1: 32 chunks x 33280
//  L2: 16 chunks x 33792  (chunk = 32 k-rows: hi 16896 + lo 16896)
#define L0_OFF   0
#define L1_OFF   66560
#define L2_OFF   1131520
#define BLK_BYTES 1672192

// smem byte offsets
#define OFF_AH   0         // activation [64 x 520] fp16 = 66560 (also fp32 park 64x260)
#define OFF_W    66560     // 2 weight slots x 67584
#define WSLOT    67584
#define OFF_IH   201728    // input tile hi [64 x 40] fp16
#define OFF_IL   206848    // input tile lo
#define SMEM_TOTAL 211968

__device__ float g_z[NS * DIMS];
__device__ __align__(16) uint8_t g_img[(size_t)NBLOCKS * BLK_BYTES];

__device__ __forceinline__ uint32_t smem_u32(const void* p) {
    return (uint32_t)__cvta_generic_to_shared(p);
}
#define CP16(s, g)  asm volatile("cp.async.cg.shared.global [%0], [%1], 16;" :: "r"(s), "l"(g))
#define CPCOMMIT()  asm volatile("cp.async.commit_group;")
#define CPWAIT0()   asm volatile("cp.async.wait_group 0;" ::: "memory")

__device__ __forceinline__ void ldm4(uint32_t* r, uint32_t a) {
    asm volatile("ldmatrix.sync.aligned.m8n8.x4.shared.b16 {%0,%1,%2,%3}, [%4];"
        : "=r"(r[0]), "=r"(r[1]), "=r"(r[2]), "=r"(r[3]) : "r"(a));
}
__device__ __forceinline__ void ldm4t(uint32_t* r, uint32_t a) {
    asm volatile("ldmatrix.sync.aligned.m8n8.x4.trans.shared.b16 {%0,%1,%2,%3}, [%4];"
        : "=r"(r[0]), "=r"(r[1]), "=r"(r[2]), "=r"(r[3]) : "r"(a));
}
__device__ __forceinline__ void mma16816(float* d, const uint32_t* a, uint32_t b0, uint32_t b1) {
    asm volatile("mma.sync.aligned.m16n8k16.row.col.f32.f16.f16.f32 "
        "{%0,%1,%2,%3}, {%4,%5,%6,%7}, {%8,%9}, {%0,%1,%2,%3};"
        : "+f"(d[0]), "+f"(d[1]), "+f"(d[2]), "+f"(d[3])
        : "r"(a[0]), "r"(a[1]), "r"(a[2]), "r"(a[3]), "r"(b0), "r"(b1));
}
__device__ __forceinline__ int insert_bit(int f, int p, int bit) {
    int lo = f & ((1 << p) - 1);
    int hi = f >> p;
    return (hi << (p + 1)) | (bit << p) | lo;
}

// ---------------- init ----------------
__global__ void init_kernel(const float* __restrict__ x, float* __restrict__ out) {
    int i = blockIdx.x * blockDim.x + threadIdx.x;
    if (i < NS * DIMS) g_z[i] = x[i];
    if (i < NS) out[i] = 0.f;
}

// ---------------- weight image prep (unchanged) ----------------
__global__ void prep_kernel(const float* __restrict__ W0,
                            const float* __restrict__ W1,
                            const float* __restrict__ W2) {
    int plane = blockIdx.x;
    int b = plane / 100, r = plane % 100;
    uint8_t* gb = g_img + (size_t)b * BLK_BYTES;
    int layer, chunk, half;
    if (r < 4)       { layer = 0; chunk = r >> 1;        half = r & 1; }
    else if (r < 68) { int q = r - 4;  layer = 1; chunk = q >> 1; half = q & 1; }
    else             { int q = r - 68; layer = 2; chunk = q >> 1; half = q & 1; }

    int rows  = (layer == 2) ? 32 : 16;
    int padc  = (layer == 2) ? PADW2 : PADW;
    int ncols = (layer == 2) ? FEAT_OUT : UNITS;
    uint8_t* dst;
    if (layer == 0)      dst = gb + L0_OFF + chunk * 33280 + half * 16640;
    else if (layer == 1) dst = gb + L1_OFF + chunk * 33280 + half * 16640;
    else                 dst = gb + L2_OFF + chunk * 33792 + half * 16896;
    __half* d16 = (__half*)dst;

    for (int i = threadIdx.x; i < rows * padc; i += blockDim.x) {
        int row = i / padc, col = i % padc;
        int k = chunk * rows + row;
        float w = 0.f;
        if (col < ncols) {
            if (layer == 0)      { if (k < FEAT_IN) w = W0[((size_t)b * FEAT_IN + k) * UNITS + col]; }
            else if (layer == 1) { w = W1[((size_t)b * UNITS + k) * UNITS + col]; }
            else                 { w = W2[((size_t)b * UNITS + k) * FEAT_OUT + col]; }
        }
        __half hi = __float2half(w);
        float v = half ? (w - __half2float(hi)) : w;
        d16[i] = __float2half(v);
    }
}

// ---------------- helpers ----------------
__device__ __forceinline__ void copy16(uint32_t sdst, const uint8_t* g, int n16, int tid) {
    for (int i = tid; i < n16; i += NTHREADS)
        CP16(sdst + i * 16, g + (size_t)i * 16);
}

// epilogue L0/L1: bias+relu -> fp16 activation tile.  warp = m64 x n32
// acc layout: acc[mh*16 + np*8 + j*4 + rr*2 + e]
__device__ __forceinline__ void epi_h(float* acc, const float* __restrict__ bias,
                                      uint8_t* sm, int nw, int lane) {
    int rq = lane >> 2;
    int c0 = (lane & 3) * 2;
    uint8_t* AH = sm + OFF_AH;
    #pragma unroll
    for (int np = 0; np < 2; np++) {
        #pragma unroll
        for (int j = 0; j < 2; j++) {
            int col = nw * 32 + np * 16 + j * 8 + c0;
            float bx = bias[col], by = bias[col + 1];
            #pragma unroll
            for (int mh = 0; mh < 4; mh++) {
                float* a = acc + mh * 16 + np * 8 + j * 4;
                #pragma unroll
                for (int rr = 0; rr < 2; rr++) {
                    float vx = fmaxf(a[rr * 2 + 0] + bx, 0.f);
                    float vy = fmaxf(a[rr * 2 + 1] + by, 0.f);
                    int row = mh * 16 + rr * 8 + rq;
                    uint32_t off = (uint32_t)(row * PADH + col) * 2;
                    *(__half2*)(AH + off) = __halves2half2(__float2half(vx), __float2half(vy));
                }
            }
        }
    }
}

// ---------------- main fused flow-block kernel ----------------
__global__ void __launch_bounds__(NTHREADS, 1)
flow_block_kernel(int blk,
                  const float* __restrict__ cc,
                  const float* __restrict__ B0, const float* __restrict__ B1,
                  const float* __restrict__ B2,
                  float* __restrict__ out)
{
    extern __shared__ __align__(128) uint8_t sm[];
    const uint32_t s0 = smem_u32(sm);
    const int tid  = threadIdx.x;
    const int wid  = tid >> 5;
    const int lane = tid & 31;
    const int nw   = wid;          // L0/L1: 16 column groups x n32
    const int mw2  = wid & 1;      // L2: 2 sample groups x m32
    const int nw2  = wid >> 1;     // L2: 8 column groups x n32
    const int row0 = blockIdx.x * MTS;
    const int p    = blk >> 1;
    const int cbit = 1 - (blk & 1);
    const uint8_t* gb = g_img + (size_t)blk * BLK_BYTES;

    const int l15  = lane & 15;
    const int lhi  = lane >> 4;
    // L0/L1 act fragment offsets: 4 m16 fragments covering m64
    uint32_t aoffM[4], ioffM[4];
    #pragma unroll
    for (int mh = 0; mh < 4; mh++) {
        aoffM[mh] = (uint32_t)((mh * 16 + l15) * (PADH * 2)) + lhi * 16;
        ioffM[mh] = (uint32_t)((mh * 16 + l15) * 80) + lhi * 16;
    }
    // L2 act fragment offsets (m32 per warp)
    const int ar2  = mw2 * 32 + l15;
    const uint32_t aoff2_0 = (uint32_t)(ar2 * (PADH * 2)) + lhi * 16;
    const uint32_t aoff2_1 = aoff2_0 + 16 * (PADH * 2);

    const int krow = (lane & 7) + ((lane >> 3) & 1) * 8;
    const uint32_t woff1 = (uint32_t)(krow * (PADW * 2))  + (uint32_t)lhi * 16;
    const uint32_t woff2 = (uint32_t)(krow * (PADW2 * 2)) + (uint32_t)lhi * 16;

    // ---- stage L0 weights (66560 B) ----
    copy16(s0 + OFF_W, gb + L0_OFF, 4160, tid);
    CPCOMMIT();

    // ---- build input tile [64 x 32] fp16 hi/lo, zero-padded ----
    for (int i = tid; i < 1280; i += NTHREADS) {
        ((uint32_t*)(sm + OFF_IH))[i] = 0u;
        ((uint32_t*)(sm + OFF_IL))[i] = 0u;
    }
    __syncthreads();
    for (int i = tid; i < MTS * FEAT_IN; i += NTHREADS) {
        int m = i / FEAT_IN, f = i % FEAT_IN;
        float v = (f < DT) ? g_z[(row0 + m) * DIMS + insert_bit(f, p, cbit)]
                           : cc[(row0 + m) * DIMSC + (f - DT)];
        __half hi = __float2half(v);
        ((__half*)(sm + OFF_IH))[m * 40 + f] = hi;
        ((__half*)(sm + OFF_IL))[m * 40 + f] = __float2half(v - __half2float(hi));
    }
    CPWAIT0();
    __syncthreads();

    float acc[64];
    #pragma unroll
    for (int i = 0; i < 64; i++) acc[i] = 0.f;

    // ---- L0: 2 k16-steps, 3-pass (ah*bh, ah*bl, al*bh), warp = m64 x n32 ----
    #pragma unroll
    for (int ks = 0; ks < 2; ks++) {
        uint32_t ah[4][4], al[4][4];
        #pragma unroll
        for (int mh = 0; mh < 4; mh++) {
            ldm4(ah[mh], s0 + OFF_IH + ioffM[mh] + ks * 32);
            ldm4(al[mh], s0 + OFF_IL + ioffM[mh] + ks * 32);
        }
        uint32_t wb = s0 + OFF_W + ks * 33280;
        #pragma unroll
        for (int np = 0; np < 2; np++) {
            uint32_t bh[4], bl[4];
            uint32_t ba = wb + woff1 + (uint32_t)(nw * 32 + np * 16) * 2;
            ldm4t(bh, ba);
            ldm4t(bl, ba + 16640);
            #pragma unroll
            for (int mh = 0; mh < 4; mh++) {
                float* d0 = acc + mh * 16 + np * 8;
                mma16816(d0,     ah[mh], bh[0], bh[1]);
                mma16816(d0 + 4, ah[mh], bh[2], bh[3]);
            }
            #pragma unroll
            for (int mh = 0; mh < 4; mh++) {
                float* d0 = acc + mh * 16 + np * 8;
                mma16816(d0,     ah[mh], bl[0], bl[1]);
                mma16816(d0 + 4, ah[mh], bl[2], bl[3]);
            }
            #pragma unroll
            for (int mh = 0; mh < 4; mh++) {
                float* d0 = acc + mh * 16 + np * 8;
                mma16816(d0,     al[mh], bh[0], bh[1]);
                mma16816(d0 + 4, al[mh], bh[2], bh[3]);
            }
        }
    }
    __syncthreads();   // L0 weight reads retired

    // ---- L1 prologue: copy chunk 0, epilogue0 overlapped ----
    copy16(s0 + OFF_W, gb + L1_OFF, 4160, tid);
    CPCOMMIT();
    epi_h(acc, B0, sm, nw, lane);
    #pragma unroll
    for (int i = 0; i < 64; i++) acc[i] = 0.f;

    // ---- L1: 16 k32-chunks, single-sync pipeline, warp = m64 x n32 ----
    for (int c = 0; c < 16; c++) {
        CPWAIT0();          // chunk c arrived
        __syncthreads();    // visible to all; prior chunk's buffer reads retired
        if (c + 1 < 16) {
            copy16(s0 + OFF_W + ((c + 1) & 1) * WSLOT,
                   gb + L1_OFF + (size_t)(c + 1) * 66560, 4160, tid);
            CPCOMMIT();
        }
        uint32_t buf = s0 + OFF_W + (c & 1) * WSLOT;
        #pragma unroll
        for (int ks2 = 0; ks2 < 2; ks2++) {
            uint32_t ah[4][4];
            uint32_t ao = (uint32_t)(c * 64 + ks2 * 32);
            #pragma unroll
            for (int mh = 0; mh < 4; mh++)
                ldm4(ah[mh], s0 + OFF_AH + aoffM[mh] + ao);
            uint32_t wb = buf + ks2 * 33280;
            #pragma unroll
            for (int np = 0; np < 2; np++) {
                uint32_t bh[4], bl[4];
                uint32_t ba = wb + woff1 + (uint32_t)(nw * 32 + np * 16) * 2;
                ldm4t(bh, ba);
                ldm4t(bl, ba + 16640);
                #pragma unroll
                for (int mh = 0; mh < 4; mh++) {
                    float* d0 = acc + mh * 16 + np * 8;
                    mma16816(d0,     ah[mh], bh[0], bh[1]);
                    mma16816(d0 + 4, ah[mh], bh[2], bh[3]);
                }
                #pragma unroll
                for (int mh = 0; mh < 4; mh++) {
                    float* d0 = acc + mh * 16 + np * 8;
                    mma16816(d0,     ah[mh], bl[0], bl[1]);
                    mma16816(d0 + 4, ah[mh], bl[2], bl[3]);
                }
            }
        }
    }
    __syncthreads();   // L1 chunk 15 compute retired (act reads done)

    // ---- L2 prologue (k64 chunk 0) + epilogue1 ----
    copy16(s0 + OFF_W, gb + L2_OFF, 4224, tid);
    CPCOMMIT();
    epi_h(acc, B1, sm, nw, lane);

    float acc2[32];
    #pragma unroll
    for (int i = 0; i < 32; i++) acc2[i] = 0.f;

    // ---- L2: 8 k64-chunks, single-sync pipeline, warp = m32 x n32 ----
    for (int c = 0; c < 8; c++) {
        CPWAIT0();
        __syncthreads();
        if (c + 1 < 8) {
            copy16(s0 + OFF_W + ((c + 1) & 1) * WSLOT,
                   gb + L2_OFF + (size_t)(c + 1) * 67584, 4224, tid);
            CPCOMMIT();
        }
        uint32_t buf = s0 + OFF_W + (c & 1) * WSLOT;
        #pragma unroll
        for (int sub = 0; sub < 2; sub++) {
            uint32_t wbs = buf + sub * 33792;
            #pragma unroll
            for (int ks = 0; ks < 2; ks++) {
                uint32_t ah0[4], ah1[4];
                uint32_t ao = (uint32_t)(c * 128 + sub * 64 + ks * 32);
                ldm4(ah0, s0 + OFF_AH + aoff2_0 + ao);
                ldm4(ah1, s0 + OFF_AH + aoff2_1 + ao);
                #pragma unroll
                for (int np = 0; np < 2; np++) {
                    uint32_t bh[4], bl[4];
                    uint32_t ba = wbs + (uint32_t)(ks * 16 * PADW2 * 2) + woff2
                                + (uint32_t)(nw2 * 32 + np * 16) * 2;
                    ldm4t(bh, ba);
                    ldm4t(bl, ba + 16896);
                    float* d00 = acc2 + np * 16;
                    float* d01 = acc2 + np * 16 + 4;
                    float* d10 = acc2 + np * 16 + 8;
                    float* d11 = acc2 + np * 16 + 12;
                    mma16816(d00, ah0, bh[0], bh[1]);
                    mma16816(d10, ah1, bh[0], bh[1]);
                    mma16816(d01, ah0, bh[2], bh[3]);
                    mma16816(d11, ah1, bh[2], bh[3]);
                    mma16816(d00, ah0, bl[0], bl[1]);
                    mma16816(d10, ah1, bl[0], bl[1]);
                    mma16816(d01, ah0, bl[2], bl[3]);
                    mma16816(d11, ah1, bl[2], bl[3]);
                }
            }
        }
    }
    __syncthreads();   // L2 act reads retired

    // ---- park params fp32 into AH region (h dead) ----
    float* park = (float*)(sm + OFF_AH);
    {
        int rb = mw2 * 32 + (lane >> 2);
        int c0 = (lane & 3) * 2;
        #pragma unroll
        for (int np = 0; np < 2; np++) {
            #pragma unroll
            for (int j = 0; j < 2; j++) {
                int col = nw2 * 32 + np * 16 + j * 8 + c0;
                #pragma unroll
                for (int mh = 0; mh < 2; mh++) {
                    float* a = acc2 + np * 16 + mh * 8 + j * 4;
                    #pragma unroll
                    for (int rr = 0; rr < 2; rr++) {
                        int row = rb + mh * 16 + rr * 8;
                        *(float2*)(park + row * 260 + col) = make_float2(a[rr * 2 + 0], a[rr * 2 + 1]);
                    }
                }
            }
        }
    }
    __syncthreads();

    // ---- spline + logdet ----
    {
        const int m2 = tid >> 3;
        const int dg = tid & 7;
        float pr[31];
        #pragma unroll
        for (int j = 0; j < 31; j++)
            pr[j] = park[m2 * 260 + dg * 31 + j] + B2[dg * 31 + j];

        const int tdim = insert_bit(dg, p, 1 - cbit);
        const float xv = g_z[(row0 + m2) * DIMS + tdim];

        float ww[BINS], hh[BINS], dd[BINS + 1];
        float mx = pr[0];
        #pragma unroll
        for (int i = 1; i < BINS; i++) mx = fmaxf(mx, pr[i]);
        float ssum = 0.f;
        #pragma unroll
        for (int i = 0; i < BINS; i++) { ww[i] = expf(pr[i] - mx); ssum += ww[i]; }
        float sc = (1.0f - MIN_W * (float)BINS) / ssum;
        #pragma unroll
        for (int i = 0; i < BINS; i++) ww[i] = MIN_W + ww[i] * sc;

        mx = pr[BINS];
        #pragma unroll
        for (int i = 1; i < BINS; i++) mx = fmaxf(mx, pr[BINS + i]);
        ssum = 0.f;
        #pragma unroll
        for (int i = 0; i < BINS; i++) { hh[i] = expf(pr[BINS + i] - mx); ssum += hh[i]; }
        sc = (1.0f - MIN_H * (float)BINS) / ssum;
        #pragma unroll
        for (int i = 0; i < BINS; i++) hh[i] = MIN_H + hh[i] * sc;

        #pragma unroll
        for (int i = 0; i <= BINS; i++) {
            float u = pr[2 * BINS + i];
            dd[i] = MIN_D + (fmaxf(u, 0.f) + log1pf(expf(-fabsf(u))));
        }

        float cw[BINS + 1], ch[BINS + 1];
        cw[0] = 0.f; ch[0] = 0.f;
        #pragma unroll
        for (int i = 1; i <= BINS; i++) { cw[i] = cw[i-1] + ww[i-1]; ch[i] = ch[i-1] + hh[i-1]; }

        int cnt = 0;
        #pragma unroll
        for (int i = 0; i <= BINS; i++) cnt += (xv >= cw[i]) ? 1 : 0;
        int idx = cnt - 1;
        idx = idx < 0 ? 0 : (idx > BINS - 1 ? BINS - 1 : idx);

        float xk = 0.f, wk = 1.f, yk = 0.f, hk = 1.f, dk = 1.f, dk1 = 1.f;
        #pragma unroll
        for (int i = 0; i < BINS; i++)
            if (i == idx) { xk = cw[i]; wk = ww[i]; yk = ch[i]; hk = hh[i]; dk = dd[i]; dk1 = dd[i+1]; }

        float th  = fminf(fmaxf((xv - xk) / wk, 0.f), 1.f);
        float sr  = hk / wk;
        float t1  = th * (1.f - th);
        float den = sr + (dk1 + dk - 2.f * sr) * t1;
        float y   = yk + hk * (sr * th * th + dk * t1) / den;
        float omt = 1.f - th;
        float ld  = 2.f * logf(sr)
                  + logf(dk1 * th * th + 2.f * sr * t1 + dk * omt * omt)
                  - 2.f * logf(den);

        g_z[(row0 + m2) * DIMS + tdim] = y;

        #pragma unroll
        for (int off = 4; off > 0; off >>= 1)
            ld += __shfl_down_sync(0xffffffffu, ld, off);
        if (dg == 0) out[row0 + m2] += ld;
    }
}

extern "C" void kernel_launch(void* const* d_in, const int* in_sizes, int n_in,
                              void* d_out, int out_size) {
    const float* x  = (const float*)d_in[0];
    const float* c  = (const float*)d_in[1];
    const float* W0 = (const float*)d_in[2];
    const float* b0 = (const float*)d_in[3];
    const float* W1 = (const float*)d_in[4];
    const float* b1 = (const float*)d_in[5];
    const float* W2 = (const float*)d_in[6];
    const float* b2 = (const float*)d_in[7];
    float* out = (float*)d_out;

    cudaFuncSetAttribute(flow_block_kernel,
                         cudaFuncAttributeMaxDynamicSharedMemorySize, SMEM_TOTAL);

    init_kernel<<<(NS * DIMS + 255) / 256, 256>>>(x, out);
    prep_kernel<<<NBLOCKS * 100, 256>>>(W0, W1, W2);

    for (int b = 0; b < NBLOCKS; b++) {
        flow_block_kernel<<<NS / MTS, NTHREADS, SMEM_TOTAL>>>(
            b, c,
            b0 + (size_t)b * UNITS,
            b1 + (size_t)b * UNITS,
            b2 + (size_t)b * FEAT_OUT,
            out);
    }
}